// round 3
// baseline (speedup 1.0000x reference)
#include <cuda_runtime.h>
#include <math.h>

#define Lc 128
#define Bc 32
#define Tc 64
#define TDc 63
#define Ec 512
#define Hc 512
#define Ac 512
#define Vc 32000
#define G3 1536
#define MBc (TDc*Bc)   // 2016

// ---------------- scratch (static device arrays; no allocation) ----------------
__device__ float d_emb   [Lc*Bc*Ec];
__device__ float d_decemb[MBc*Ec];
__device__ float d_gi    [2*Lc*Bc*G3];       // reused: layer0 then layer1
__device__ float d_y0    [Lc*Bc*2*Hc];
__device__ float d_y1    [Lc*Bc*2*Hc];
__device__ float d_eo    [Lc*Bc*Hc];         // enc_out [L,B,H]
__device__ float d_eq    [Lc*Bc*Ac];         // enc_q   [L,B,A]
__device__ float d_dpre  [MBc*G3];
__device__ float d_h0b   [2*Bc*Hc];
__device__ float d_h1b   [2*Bc*Hc];
__device__ float d_ctxb  [2*Bc*Hc];
__device__ float d_qb    [Bc*Ac];
__device__ float d_feat  [MBc*2*Hc];
__device__ float d_hid   [MBc*2*Hc];

// ---------------- embedding gathers ----------------
__global__ void gather_rows(const int* __restrict__ tok, const float* __restrict__ tab,
                            float* __restrict__ out, int mode)
{
    int row = blockIdx.x;
    int idx;
    if (mode == 0) idx = tok[row];                       // enc: row = t*B+b, src_tokens[t*B+b]
    else { int t = row >> 5, b = row & 31; idx = tok[b*Tc + t]; }  // dec: prev[t,b]=trgt[b,t]
    const float4* src = (const float4*)(tab + (size_t)idx * Ec);
    float4* dst = (float4*)(out + (size_t)row * Ec);
    dst[threadIdx.x] = src[threadIdx.x];                 // 128 threads * float4 = 512
}

// ---------------- generic SGEMM: C = A @ W^T + bias ----------------
// flags bit0: relu, bit1: remap output row m -> (m&31)*63 + (m>>5)
__global__ __launch_bounds__(256) void sgemm128(
    int M, int N, int K,
    const float* __restrict__ A, int lda,
    const float* __restrict__ W, int ldw,
    const float* __restrict__ bias,
    float* __restrict__ C, int ldc, int flags)
{
    __shared__ float As[8][128];
    __shared__ float Ws[8][128];
    const int tid = threadIdx.x;
    const int mBase = blockIdx.y * 128;
    const int nBase = blockIdx.x * 128;
    const int loadRow = tid >> 1;
    const int loadCol = (tid & 1) << 2;
    const int tx = tid & 15;
    const int ty = tid >> 4;

    float acc[8][8];
    #pragma unroll
    for (int i = 0; i < 8; i++)
        #pragma unroll
        for (int j = 0; j < 8; j++) acc[i][j] = 0.f;

    for (int k0 = 0; k0 < K; k0 += 8) {
        float4 av = make_float4(0,0,0,0), wv = make_float4(0,0,0,0);
        int am = mBase + loadRow;
        if (am < M) av = *(const float4*)(A + (size_t)am*lda + k0 + loadCol);
        int wn = nBase + loadRow;
        if (wn < N) wv = *(const float4*)(W + (size_t)wn*ldw + k0 + loadCol);
        As[loadCol+0][loadRow]=av.x; As[loadCol+1][loadRow]=av.y;
        As[loadCol+2][loadRow]=av.z; As[loadCol+3][loadRow]=av.w;
        Ws[loadCol+0][loadRow]=wv.x; Ws[loadCol+1][loadRow]=wv.y;
        Ws[loadCol+2][loadRow]=wv.z; Ws[loadCol+3][loadRow]=wv.w;
        __syncthreads();
        #pragma unroll
        for (int kk = 0; kk < 8; kk++) {
            float ra[8], rb[8];
            *(float4*)&ra[0] = *(const float4*)&As[kk][ty*4];
            *(float4*)&ra[4] = *(const float4*)&As[kk][64 + ty*4];
            *(float4*)&rb[0] = *(const float4*)&Ws[kk][tx*4];
            *(float4*)&rb[4] = *(const float4*)&Ws[kk][64 + tx*4];
            #pragma unroll
            for (int i = 0; i < 8; i++)
                #pragma unroll
                for (int j = 0; j < 8; j++) acc[i][j] += ra[i]*rb[j];
        }
        __syncthreads();
    }

    #pragma unroll
    for (int i = 0; i < 8; i++) {
        int m = mBase + ((i < 4) ? (ty*4 + i) : (64 + ty*4 + i - 4));
        if (m >= M) continue;
        int orow = (flags & 2) ? ((m & 31)*TDc + (m >> 5)) : m;
        #pragma unroll
        for (int j = 0; j < 8; j++) {
            int n = nBase + ((j < 4) ? (tx*4 + j) : (64 + tx*4 + j - 4));
            if (n >= N) continue;
            float v = acc[i][j] + (bias ? bias[n] : 0.f);
            if (flags & 1) v = fmaxf(v, 0.f);
            C[(size_t)orow*ldc + n] = v;
        }
    }
}

// ---------------- fused encoder GRU recurrent step (both dirs via blockIdx.y) ----------------
__global__ __launch_bounds__(256) void gru_step(
    const float* __restrict__ giBase,    // [2][L*B][1536] (includes bih)
    const float* __restrict__ WhhBase,   // [2][1536][512]
    const float* __restrict__ bhhBase,   // [2][1536]
    float* __restrict__ y,               // [L,B,1024] fwd cols 0:512, bwd 512:1024
    int s)
{
    const int dir = blockIdx.y;
    const int tid = threadIdx.x;
    const int row = tid & 31;
    const int j   = blockIdx.x * 8 + (tid >> 5);
    const int te    = dir ? (Lc - 1 - s) : s;
    const int tprev = dir ? (te + 1) : (te - 1);
    const bool first = (s == 0);
    const int dcol = dir * Hc;
    const float* gi  = giBase  + (size_t)dir * Lc * Bc * G3;
    const float* Whh = WhhBase + (size_t)dir * G3 * Hc;
    const float* bhh = bhhBase + dir * G3;

    __shared__ float hs[32][136];
    float ar = 0.f, az = 0.f, an = 0.f;
    const float* wr = Whh + (size_t)j * Hc;
    const float* wz = Whh + (size_t)(Hc  + j) * Hc;
    const float* wn = Whh + (size_t)(2*Hc + j) * Hc;

    for (int kc = 0; kc < Hc; kc += 128) {
        for (int i = tid; i < 1024; i += 256) {
            int r = i >> 5, kk = (i & 31) << 2;
            float4 v = make_float4(0,0,0,0);
            if (!first) v = *(const float4*)&y[((size_t)tprev*Bc + r)*(2*Hc) + dcol + kc + kk];
            *(float4*)&hs[r][kk] = v;
        }
        __syncthreads();
        #pragma unroll 8
        for (int k = 0; k < 128; k += 4) {
            float4 hv = *(const float4*)&hs[row][k];
            float4 w;
            w = *(const float4*)&wr[kc+k]; ar += hv.x*w.x + hv.y*w.y + hv.z*w.z + hv.w*w.w;
            w = *(const float4*)&wz[kc+k]; az += hv.x*w.x + hv.y*w.y + hv.z*w.z + hv.w*w.w;
            w = *(const float4*)&wn[kc+k]; an += hv.x*w.x + hv.y*w.y + hv.z*w.z + hv.w*w.w;
        }
        __syncthreads();
    }

    const float* g = gi + ((size_t)te*Bc + row) * G3;
    float gr = g[j], gz = g[Hc + j], gn = g[2*Hc + j];
    float hr = ar + bhh[j], hz = az + bhh[Hc + j], hn = an + bhh[2*Hc + j];
    float rg = 1.f / (1.f + __expf(-(gr + hr)));
    float zg = 1.f / (1.f + __expf(-(gz + hz)));
    float ng = tanhf(gn + rg * hn);
    float hp = first ? 0.f : y[((size_t)tprev*Bc + row)*(2*Hc) + dcol + j];
    y[((size_t)te*Bc + row)*(2*Hc) + dcol + j] = (1.f - zg)*ng + zg*hp;
}

// ---------------- enc_out = y1[:, :H] + y1[:, H:] ----------------
__global__ void combine_enc(const float* __restrict__ y1, float* __restrict__ eo)
{
    int i = blockIdx.x;
    int h = threadIdx.x * 4;
    float4 a = *(const float4*)&y1[(size_t)i*2*Hc + h];
    float4 b = *(const float4*)&y1[(size_t)i*2*Hc + Hc + h];
    float4 c = make_float4(a.x+b.x, a.y+b.y, a.z+b.z, a.w+b.w);
    *(float4*)&eo[(size_t)i*Hc + h] = c;
}

// ---------------- fused decoder GRU cell: gates from x@Wx^T + h@Whh^T (+pre, +biases) --------
__global__ __launch_bounds__(256) void dec_cell(
    const float* __restrict__ x,   const float* __restrict__ Wx, int ldx,
    const float* __restrict__ hin, const float* __restrict__ Whh,
    const float* __restrict__ pre,   // [32][1536] or null (includes bih)
    const float* __restrict__ bi,    // [1536] or null
    const float* __restrict__ bh,
    float* __restrict__ hout)
{
    const int tid = threadIdx.x;
    const int row = tid & 31;
    const int j   = blockIdx.x * 8 + (tid >> 5);
    __shared__ float hs[32][136];
    float air=0.f, aiz=0.f, ain=0.f, ahr=0.f, ahz=0.f, ahn=0.f;
    const float* wxr = Wx + (size_t)j * ldx;
    const float* wxz = Wx + (size_t)(Hc  + j) * ldx;
    const float* wxn = Wx + (size_t)(2*Hc + j) * ldx;
    const float* whr = Whh + (size_t)j * Hc;
    const float* whz = Whh + (size_t)(Hc  + j) * Hc;
    const float* whn = Whh + (size_t)(2*Hc + j) * Hc;

    for (int kc = 0; kc < Hc; kc += 128) {
        for (int i = tid; i < 1024; i += 256) {
            int r = i >> 5, kk = (i & 31) << 2;
            *(float4*)&hs[r][kk] = *(const float4*)&x[(size_t)r*Hc + kc + kk];
        }
        __syncthreads();
        #pragma unroll 8
        for (int k = 0; k < 128; k += 4) {
            float4 hv = *(const float4*)&hs[row][k];
            float4 w;
            w = *(const float4*)&wxr[kc+k]; air += hv.x*w.x + hv.y*w.y + hv.z*w.z + hv.w*w.w;
            w = *(const float4*)&wxz[kc+k]; aiz += hv.x*w.x + hv.y*w.y + hv.z*w.z + hv.w*w.w;
            w = *(const float4*)&wxn[kc+k]; ain += hv.x*w.x + hv.y*w.y + hv.z*w.z + hv.w*w.w;
        }
        __syncthreads();
    }
    for (int kc = 0; kc < Hc; kc += 128) {
        for (int i = tid; i < 1024; i += 256) {
            int r = i >> 5, kk = (i & 31) << 2;
            *(float4*)&hs[r][kk] = *(const float4*)&hin[(size_t)r*Hc + kc + kk];
        }
        __syncthreads();
        #pragma unroll 8
        for (int k = 0; k < 128; k += 4) {
            float4 hv = *(const float4*)&hs[row][k];
            float4 w;
            w = *(const float4*)&whr[kc+k]; ahr += hv.x*w.x + hv.y*w.y + hv.z*w.z + hv.w*w.w;
            w = *(const float4*)&whz[kc+k]; ahz += hv.x*w.x + hv.y*w.y + hv.z*w.z + hv.w*w.w;
            w = *(const float4*)&whn[kc+k]; ahn += hv.x*w.x + hv.y*w.y + hv.z*w.z + hv.w*w.w;
        }
        __syncthreads();
    }

    float gir = air, giz = aiz, gin = ain;
    if (pre) { const float* p = pre + (size_t)row * G3; gir += p[j]; giz += p[Hc+j]; gin += p[2*Hc+j]; }
    if (bi)  { gir += bi[j]; giz += bi[Hc+j]; gin += bi[2*Hc+j]; }
    float ghr = ahr + bh[j], ghz = ahz + bh[Hc+j], ghn = ahn + bh[2*Hc+j];
    float rg = 1.f / (1.f + __expf(-(gir + ghr)));
    float zg = 1.f / (1.f + __expf(-(giz + ghz)));
    float ng = tanhf(gin + rg * ghn);
    hout[(size_t)row*Hc + j] = (1.f - zg)*ng + zg*hin[(size_t)row*Hc + j];
}

// ---------------- q = h1 @ Wd^T + bd ----------------
__global__ __launch_bounds__(256) void linear_q(
    const float* __restrict__ x, const float* __restrict__ Wd,
    const float* __restrict__ bd, float* __restrict__ q)
{
    const int tid = threadIdx.x;
    const int row = tid & 31;
    const int j   = blockIdx.x * 8 + (tid >> 5);
    __shared__ float hs[32][136];
    float acc = 0.f;
    const float* wj = Wd + (size_t)j * Hc;
    for (int kc = 0; kc < Hc; kc += 128) {
        for (int i = tid; i < 1024; i += 256) {
            int r = i >> 5, kk = (i & 31) << 2;
            *(float4*)&hs[r][kk] = *(const float4*)&x[(size_t)r*Hc + kc + kk];
        }
        __syncthreads();
        #pragma unroll 8
        for (int k = 0; k < 128; k += 4) {
            float4 hv = *(const float4*)&hs[row][k];
            float4 w  = *(const float4*)&wj[kc+k];
            acc += hv.x*w.x + hv.y*w.y + hv.z*w.z + hv.w*w.w;
        }
        __syncthreads();
    }
    q[(size_t)row*Hc + j] = acc + bd[j];
}

// ---------------- attention: e = tanh(enc_q . q), softmax, ctx; emit feat rows ---------------
__global__ __launch_bounds__(256) void attn_step(
    const float* __restrict__ q,       // [32,512]
    const float* __restrict__ encq,    // [L,B,512]
    const float* __restrict__ encout,  // [L,B,512]
    const float* __restrict__ h1,      // [32,512]
    float* __restrict__ ctxout,        // [32,512]
    float* __restrict__ feat)          // base offset t*B*1024 applied by caller; rows = b
{
    const int b = blockIdx.x, tid = threadIdx.x, lane = tid & 31, w = tid >> 5;
    __shared__ float qs[512];
    __shared__ float es[128];
    __shared__ float ssum[4];
    qs[tid] = q[(size_t)b*Hc + tid];
    qs[tid + 256] = q[(size_t)b*Hc + tid + 256];
    __syncthreads();

    for (int l = w; l < Lc; l += 8) {
        const float* eqr = encq + ((size_t)l*Bc + b) * Ac;
        float s = 0.f;
        #pragma unroll
        for (int qk = 0; qk < 4; qk++) {
            int k = qk*128 + lane*4;
            float4 a = *(const float4*)&eqr[k];
            float4 c = *(const float4*)&qs[k];
            s += a.x*c.x + a.y*c.y + a.z*c.z + a.w*c.w;
        }
        #pragma unroll
        for (int off = 16; off; off >>= 1) s += __shfl_xor_sync(0xffffffffu, s, off);
        if (lane == 0) es[l] = __expf(tanhf(s));   // tanh keeps e in [-1,1]; softmax is stable
    }
    __syncthreads();
    if (tid < 128) {
        float v = es[tid];
        #pragma unroll
        for (int off = 16; off; off >>= 1) v += __shfl_xor_sync(0xffffffffu, v, off);
        if (lane == 0) ssum[tid >> 5] = v;
    }
    __syncthreads();
    float inv = 1.f / (ssum[0] + ssum[1] + ssum[2] + ssum[3]);

    float a0 = 0.f, a1 = 0.f;
    for (int l = 0; l < Lc; l++) {
        float wl = es[l];
        const float* eo = encout + ((size_t)l*Bc + b) * Hc;
        a0 += wl * eo[tid];
        a1 += wl * eo[tid + 256];
    }
    a0 *= inv; a1 *= inv;
    ctxout[(size_t)b*Hc + tid]       = a0;
    ctxout[(size_t)b*Hc + tid + 256] = a1;
    feat[(size_t)b*2*Hc + tid]             = h1[(size_t)b*Hc + tid];
    feat[(size_t)b*2*Hc + tid + 256]       = h1[(size_t)b*Hc + tid + 256];
    feat[(size_t)b*2*Hc + Hc + tid]        = a0;
    feat[(size_t)b*2*Hc + Hc + tid + 256]  = a1;
}

// ================================================================================
extern "C" void kernel_launch(void* const* d_in, const int* in_sizes, int n_in,
                              void* d_out, int out_size)
{
    const int*   src_tokens = (const int*)  d_in[0];
    const int*   trgt_seq   = (const int*)  d_in[1];
    const float* enc_embed  = (const float*)d_in[3];
    const float* enc_Wih0   = (const float*)d_in[4];
    const float* enc_Whh0   = (const float*)d_in[5];
    const float* enc_bih0   = (const float*)d_in[6];
    const float* enc_bhh0   = (const float*)d_in[7];
    const float* enc_Wih1   = (const float*)d_in[8];
    const float* enc_Whh1   = (const float*)d_in[9];
    const float* enc_bih1   = (const float*)d_in[10];
    const float* enc_bhh1   = (const float*)d_in[11];
    const float* dec_embed  = (const float*)d_in[12];
    const float* dec_Wih0   = (const float*)d_in[13];
    const float* dec_Whh0   = (const float*)d_in[14];
    const float* dec_bih0   = (const float*)d_in[15];
    const float* dec_bhh0   = (const float*)d_in[16];
    const float* dec_Wih1   = (const float*)d_in[17];
    const float* dec_Whh1   = (const float*)d_in[18];
    const float* dec_bih1   = (const float*)d_in[19];
    const float* dec_bhh1   = (const float*)d_in[20];
    const float* attn_We    = (const float*)d_in[21];
    const float* attn_be    = (const float*)d_in[22];
    const float* attn_Wd    = (const float*)d_in[23];
    const float* attn_bd    = (const float*)d_in[24];
    const float* mlp_W1     = (const float*)d_in[25];
    const float* mlp_b1     = (const float*)d_in[26];
    const float* mlp_W2     = (const float*)d_in[27];
    const float* mlp_b2     = (const float*)d_in[28];

    float *emb, *decemb, *gi, *y0, *y1, *eo, *eq, *dpre, *h0b, *h1b, *ctxb, *qb, *feat, *hid;
    cudaGetSymbolAddress((void**)&emb,    d_emb);
    cudaGetSymbolAddress((void**)&decemb, d_decemb);
    cudaGetSymbolAddress((void**)&gi,     d_gi);
    cudaGetSymbolAddress((void**)&y0,     d_y0);
    cudaGetSymbolAddress((void**)&y1,     d_y1);
    cudaGetSymbolAddress((void**)&eo,     d_eo);
    cudaGetSymbolAddress((void**)&eq,     d_eq);
    cudaGetSymbolAddress((void**)&dpre,   d_dpre);
    cudaGetSymbolAddress((void**)&h0b,    d_h0b);
    cudaGetSymbolAddress((void**)&h1b,    d_h1b);
    cudaGetSymbolAddress((void**)&ctxb,   d_ctxb);
    cudaGetSymbolAddress((void**)&qb,     d_qb);
    cudaGetSymbolAddress((void**)&feat,   d_feat);
    cudaGetSymbolAddress((void**)&hid,    d_hid);

    // zero initial decoder states (buffers with index 0)
    cudaMemsetAsync(h0b,  0, Bc*Hc*sizeof(float));
    cudaMemsetAsync(h1b,  0, Bc*Hc*sizeof(float));
    cudaMemsetAsync(ctxb, 0, Bc*Hc*sizeof(float));

    // embeddings
    gather_rows<<<Lc*Bc, 128>>>(src_tokens, enc_embed, emb, 0);
    gather_rows<<<MBc,   128>>>(trgt_seq,   dec_embed, decemb, 1);

    // encoder layer0: hoisted input projections, then 128 recurrent steps (both dirs)
    for (int d = 0; d < 2; d++)
        sgemm128<<<dim3(G3/128, (Lc*Bc)/128), 256>>>(Lc*Bc, G3, Ec,
            emb, Ec, enc_Wih0 + (size_t)d*G3*Ec, Ec, enc_bih0 + d*G3,
            gi + (size_t)d*Lc*Bc*G3, G3, 0);
    for (int s = 0; s < Lc; s++)
        gru_step<<<dim3(64, 2), 256>>>(gi, enc_Whh0, enc_bhh0, y0, s);

    // encoder layer1
    for (int d = 0; d < 2; d++)
        sgemm128<<<dim3(G3/128, (Lc*Bc)/128), 256>>>(Lc*Bc, G3, 2*Hc,
            y0, 2*Hc, enc_Wih1 + (size_t)d*G3*2*Hc, 2*Hc, enc_bih1 + d*G3,
            gi + (size_t)d*Lc*Bc*G3, G3, 0);
    for (int s = 0; s < Lc; s++)
        gru_step<<<dim3(64, 2), 256>>>(gi, enc_Whh1, enc_bhh1, y1, s);

    combine_enc<<<Lc*Bc, 128>>>(y1, eo);

    // enc_q = enc_out @ We^T + be
    sgemm128<<<dim3(Ac/128, (Lc*Bc)/128), 256>>>(Lc*Bc, Ac, Hc,
        eo, Hc, attn_We, Hc, attn_be, eq, Ac, 0);

    // decoder: hoisted embed projection (includes bih0)
    sgemm128<<<dim3(G3/128, (MBc+127)/128), 256>>>(MBc, G3, Ec,
        decemb, Ec, dec_Wih0, Ec + Hc, dec_bih0, dpre, G3, 0);

    // 63 recurrent decoder steps (ping-pong state buffers)
    for (int t = 0; t < TDc; t++) {
        int r = t & 1, wix = 1 - r;
        dec_cell<<<64, 256>>>(ctxb + (size_t)r*Bc*Hc, dec_Wih0 + Hc, Ec + Hc,
                              h0b + (size_t)r*Bc*Hc, dec_Whh0,
                              dpre + (size_t)t*Bc*G3, nullptr, dec_bhh0,
                              h0b + (size_t)wix*Bc*Hc);
        dec_cell<<<64, 256>>>(h0b + (size_t)wix*Bc*Hc, dec_Wih1, Hc,
                              h1b + (size_t)r*Bc*Hc, dec_Whh1,
                              nullptr, dec_bih1, dec_bhh1,
                              h1b + (size_t)wix*Bc*Hc);
        linear_q<<<64, 256>>>(h1b + (size_t)wix*Bc*Hc, attn_Wd, attn_bd, qb);
        attn_step<<<Bc, 256>>>(qb, eq, eo, h1b + (size_t)wix*Bc*Hc,
                               ctxb + (size_t)wix*Bc*Hc, feat + (size_t)t*Bc*2*Hc);
    }

    // batched MLP over all 2016 (t,b) rows
    sgemm128<<<dim3((2*Hc)/128, (MBc+127)/128), 256>>>(MBc, 2*Hc, 2*Hc,
        feat, 2*Hc, mlp_W1, 2*Hc, mlp_b1, hid, 2*Hc, 1 /*relu*/);
    sgemm128<<<dim3(Vc/128, (MBc+127)/128), 256>>>(MBc, Vc, 2*Hc,
        hid, 2*Hc, mlp_W2, 2*Hc, mlp_b2, (float*)d_out, Vc, 2 /*remap rows*/);
}

// round 6
// speedup vs baseline: 1.0832x; 1.0832x over previous
#include <cuda_runtime.h>
#include <cuda_bf16.h>
#include <cstdint>
#include <math.h>

#define Lc 128
#define Bc 32
#define Tc 64
#define TDc 63
#define Ec 512
#define Hc 512
#define Ac 512
#define Vc 32000
#define G3 1536
#define MBc (TDc*Bc)   // 2016
#define MPAD 2048      // padded M for tensor GEMM

// ---------------- scratch (static device arrays; no allocation) ----------------
__device__ float d_emb   [Lc*Bc*Ec];
__device__ float d_decemb[MBc*Ec];
__device__ float d_gi    [2*Lc*Bc*G3];
__device__ float d_y0    [Lc*Bc*2*Hc];
__device__ float d_y1    [Lc*Bc*2*Hc];
__device__ float d_eo    [Lc*Bc*Hc];
__device__ float d_eq    [Lc*Bc*Ac];
__device__ float d_dpre  [MBc*G3];
__device__ float d_h0b   [2*Bc*Hc];
__device__ float d_h1b   [2*Bc*Hc];
__device__ float d_ctxb  [2*Bc*Hc];
__device__ float d_qb    [Bc*Ac];
__device__ float d_feat  [MBc*2*Hc];
__device__ float d_hid   [MBc*2*Hc];
// split-bf16 operands for tensor-core logits GEMM
__device__ __nv_bfloat16 d_Ah[MPAD*1024];
__device__ __nv_bfloat16 d_Al[MPAD*1024];
__device__ __nv_bfloat16 d_Bh[(size_t)Vc*1024];
__device__ __nv_bfloat16 d_Bl[(size_t)Vc*1024];

// ---------------- embedding gathers ----------------
__global__ void gather_rows(const int* __restrict__ tok, const float* __restrict__ tab,
                            float* __restrict__ out, int mode)
{
    int row = blockIdx.x;
    int idx;
    if (mode == 0) idx = tok[row];
    else { int t = row >> 5, b = row & 31; idx = tok[b*Tc + t]; }
    const float4* src = (const float4*)(tab + (size_t)idx * Ec);
    float4* dst = (float4*)(out + (size_t)row * Ec);
    dst[threadIdx.x] = src[threadIdx.x];
}

// ---------------- fp32 -> split bf16 (hi + lo), with zero-padded tail ----------------
__global__ void conv_split(const float* __restrict__ in, __nv_bfloat16* __restrict__ hi,
                           __nv_bfloat16* __restrict__ lo, long n_valid, long n_total)
{
    long i = (long)blockIdx.x * blockDim.x + threadIdx.x;
    if (i >= n_total) return;
    float v = (i < n_valid) ? in[i] : 0.f;
    __nv_bfloat16 h = __float2bfloat16(v);
    hi[i] = h;
    lo[i] = __float2bfloat16(v - __bfloat162float(h));
}

// ---------------- generic SGEMM: C = A @ W^T + bias (fp32 SIMT) ----------------
__global__ __launch_bounds__(256) void sgemm128(
    int M, int N, int K,
    const float* __restrict__ A, int lda,
    const float* __restrict__ W, int ldw,
    const float* __restrict__ bias,
    float* __restrict__ C, int ldc, int flags)
{
    __shared__ float As[8][128];
    __shared__ float Ws[8][128];
    const int tid = threadIdx.x;
    const int mBase = blockIdx.y * 128;
    const int nBase = blockIdx.x * 128;
    const int loadRow = tid >> 1;
    const int loadCol = (tid & 1) << 2;
    const int tx = tid & 15;
    const int ty = tid >> 4;

    float acc[8][8];
    #pragma unroll
    for (int i = 0; i < 8; i++)
        #pragma unroll
        for (int j = 0; j < 8; j++) acc[i][j] = 0.f;

    for (int k0 = 0; k0 < K; k0 += 8) {
        float4 av = make_float4(0,0,0,0), wv = make_float4(0,0,0,0);
        int am = mBase + loadRow;
        if (am < M) av = *(const float4*)(A + (size_t)am*lda + k0 + loadCol);
        int wn = nBase + loadRow;
        if (wn < N) wv = *(const float4*)(W + (size_t)wn*ldw + k0 + loadCol);
        As[loadCol+0][loadRow]=av.x; As[loadCol+1][loadRow]=av.y;
        As[loadCol+2][loadRow]=av.z; As[loadCol+3][loadRow]=av.w;
        Ws[loadCol+0][loadRow]=wv.x; Ws[loadCol+1][loadRow]=wv.y;
        Ws[loadCol+2][loadRow]=wv.z; Ws[loadCol+3][loadRow]=wv.w;
        __syncthreads();
        #pragma unroll
        for (int kk = 0; kk < 8; kk++) {
            float ra[8], rb[8];
            *(float4*)&ra[0] = *(const float4*)&As[kk][ty*4];
            *(float4*)&ra[4] = *(const float4*)&As[kk][64 + ty*4];
            *(float4*)&rb[0] = *(const float4*)&Ws[kk][tx*4];
            *(float4*)&rb[4] = *(const float4*)&Ws[kk][64 + tx*4];
            #pragma unroll
            for (int i = 0; i < 8; i++)
                #pragma unroll
                for (int j = 0; j < 8; j++) acc[i][j] += ra[i]*rb[j];
        }
        __syncthreads();
    }

    #pragma unroll
    for (int i = 0; i < 8; i++) {
        int m = mBase + ((i < 4) ? (ty*4 + i) : (64 + ty*4 + i - 4));
        if (m >= M) continue;
        int orow = (flags & 2) ? ((m & 31)*TDc + (m >> 5)) : m;
        #pragma unroll
        for (int j = 0; j < 8; j++) {
            int n = nBase + ((j < 4) ? (tx*4 + j) : (64 + tx*4 + j - 4));
            if (n >= N) continue;
            float v = acc[i][j] + (bias ? bias[n] : 0.f);
            if (flags & 1) v = fmaxf(v, 0.f);
            C[(size_t)orow*ldc + n] = v;
        }
    }
}

// =============== bf16 mma.sync logits GEMM: out = remap(A @ B^T) + bias ===============
// Split-bf16 3-term: D += Ah*Bh + Ah*Bl + Al*Bh  (fp32 accum; dropped Al*Bl ~ 2^-16 rel)
// Block tile 128x128, BK=32. 8 warps: 2 (M) x 4 (N); warp tile 64x32.
__device__ __forceinline__ uint32_t smem_u32(const void* p) {
    uint32_t a;
    asm("{ .reg .u64 t; cvta.to.shared.u64 t, %1; cvt.u32.u64 %0, t; }" : "=r"(a) : "l"(p));
    return a;
}
__device__ __forceinline__ void ldm4(uint32_t& r0, uint32_t& r1, uint32_t& r2, uint32_t& r3, uint32_t a) {
    asm volatile("ldmatrix.sync.aligned.m8n8.x4.shared.b16 {%0,%1,%2,%3}, [%4];"
                 : "=r"(r0), "=r"(r1), "=r"(r2), "=r"(r3) : "r"(a));
}
__device__ __forceinline__ void mma16816(float* c, const uint32_t* a, const uint32_t* b) {
    asm volatile("mma.sync.aligned.m16n8k16.row.col.f32.bf16.bf16.f32 "
                 "{%0,%1,%2,%3},{%4,%5,%6,%7},{%8,%9},{%0,%1,%2,%3};"
                 : "+f"(c[0]), "+f"(c[1]), "+f"(c[2]), "+f"(c[3])
                 : "r"(a[0]), "r"(a[1]), "r"(a[2]), "r"(a[3]), "r"(b[0]), "r"(b[1]));
}

#define SLDA 40   // smem row stride in bf16 elems (80B: conflict-free ldmatrix)

__global__ __launch_bounds__(256) void mma_logits(
    const __nv_bfloat16* __restrict__ Ah, const __nv_bfloat16* __restrict__ Al,
    const __nv_bfloat16* __restrict__ Bh, const __nv_bfloat16* __restrict__ Bl,
    const float* __restrict__ bias, float* __restrict__ out)
{
    __shared__ __nv_bfloat16 sAh[128][SLDA], sAl[128][SLDA];
    __shared__ __nv_bfloat16 sBh[128][SLDA], sBl[128][SLDA];

    const int tid = threadIdx.x, wid = tid >> 5, lane = tid & 31;
    const int nBase = blockIdx.x * 128;
    const int mBase = blockIdx.y * 128;
    const int warpM = (wid & 1) * 64;    // 2 M-warps
    const int warpN = (wid >> 1) * 32;   // 4 N-warps

    const uint32_t bAh = smem_u32(sAh), bAl = smem_u32(sAl);
    const uint32_t bBh = smem_u32(sBh), bBl = smem_u32(sBl);

    float acc[4][4][4];
    #pragma unroll
    for (int i = 0; i < 4; i++)
        #pragma unroll
        for (int j = 0; j < 4; j++)
            #pragma unroll
            for (int e = 0; e < 4; e++) acc[i][j][e] = 0.f;

    // per-lane ldmatrix address offsets (elements)
    const int aRow = (lane & 15), aK = (lane >> 4) * 8;                 // A tiles
    const int bRow = ((lane >> 4) << 3) + (lane & 7), bK = ((lane >> 3) & 1) * 8;  // B tiles

    const __nv_bfloat16* gA[2] = { Ah + (size_t)mBase * 1024, Al + (size_t)mBase * 1024 };
    const __nv_bfloat16* gB[2] = { Bh + (size_t)nBase * 1024, Bl + (size_t)nBase * 1024 };
    __nv_bfloat16* sA[2] = { &sAh[0][0], &sAl[0][0] };
    __nv_bfloat16* sB[2] = { &sBh[0][0], &sBl[0][0] };

    for (int kc = 0; kc < 1024; kc += 32) {
        // fill smem: 4 operand tiles of 128x32 bf16; 512 int4 segs each, 2 per thread
        #pragma unroll
        for (int op = 0; op < 2; op++) {
            #pragma unroll
            for (int half = 0; half < 2; half++) {
                int s = tid + half * 256;
                int row = s >> 2, sc = s & 3;
                *(int4*)&sA[op][row * SLDA + sc * 8] =
                    *(const int4*)(gA[op] + (size_t)row * 1024 + kc + sc * 8);
                *(int4*)&sB[op][row * SLDA + sc * 8] =
                    *(const int4*)(gB[op] + (size_t)row * 1024 + kc + sc * 8);
            }
        }
        __syncthreads();

        #pragma unroll
        for (int ks = 0; ks < 2; ks++) {
            const int kb = ks * 16;
            // B fragments: 4 n8 tiles x 2 regs, for hi and lo
            uint32_t fbh[4][2], fbl[4][2];
            #pragma unroll
            for (int nt = 0; nt < 2; nt++) {
                uint32_t off = ((uint32_t)(warpN + nt * 16 + bRow) * SLDA + kb + bK) * 2;
                ldm4(fbh[nt*2][0], fbh[nt*2][1], fbh[nt*2+1][0], fbh[nt*2+1][1], bBh + off);
                ldm4(fbl[nt*2][0], fbl[nt*2][1], fbl[nt*2+1][0], fbl[nt*2+1][1], bBl + off);
            }
            #pragma unroll
            for (int mi = 0; mi < 4; mi++) {
                uint32_t fah[4], fal[4];
                uint32_t off = ((uint32_t)(warpM + mi * 16 + aRow) * SLDA + kb + aK) * 2;
                ldm4(fah[0], fah[1], fah[2], fah[3], bAh + off);
                ldm4(fal[0], fal[1], fal[2], fal[3], bAl + off);
                #pragma unroll
                for (int ni = 0; ni < 4; ni++) {
                    mma16816(acc[mi][ni], fah, fbh[ni]);
                    mma16816(acc[mi][ni], fah, fbl[ni]);
                    mma16816(acc[mi][ni], fal, fbh[ni]);
                }
            }
        }
        __syncthreads();
    }

    // epilogue: bias + remap(m) -> out row, guard m < MBc
    const int mLane = lane >> 2;           // row within 8
    const int nLane = (lane & 3) * 2;      // col pair
    #pragma unroll
    for (int mi = 0; mi < 4; mi++) {
        #pragma unroll
        for (int half = 0; half < 2; half++) {
            int m = mBase + warpM + mi * 16 + mLane + half * 8;
            if (m >= MBc) continue;
            int orow = (m & 31) * TDc + (m >> 5);
            float* orp = out + (size_t)orow * Vc;
            #pragma unroll
            for (int ni = 0; ni < 4; ni++) {
                int n = nBase + warpN + ni * 8 + nLane;
                float2 v;
                v.x = acc[mi][ni][half * 2 + 0] + bias[n];
                v.y = acc[mi][ni][half * 2 + 1] + bias[n + 1];
                *(float2*)(orp + n) = v;
            }
        }
    }
}

// ---------------- fused encoder GRU recurrent step (both dirs via blockIdx.y) ----------------
__global__ __launch_bounds__(256) void gru_step(
    const float* __restrict__ giBase, const float* __restrict__ WhhBase,
    const float* __restrict__ bhhBase, float* __restrict__ y, int s)
{
    const int dir = blockIdx.y;
    const int tid = threadIdx.x;
    const int row = tid & 31;
    const int j   = blockIdx.x * 8 + (tid >> 5);
    const int te    = dir ? (Lc - 1 - s) : s;
    const int tprev = dir ? (te + 1) : (te - 1);
    const bool first = (s == 0);
    const int dcol = dir * Hc;
    const float* gi  = giBase  + (size_t)dir * Lc * Bc * G3;
    const float* Whh = WhhBase + (size_t)dir * G3 * Hc;
    const float* bhh = bhhBase + dir * G3;

    __shared__ float hs[32][136];
    float ar = 0.f, az = 0.f, an = 0.f;
    const float* wr = Whh + (size_t)j * Hc;
    const float* wz = Whh + (size_t)(Hc  + j) * Hc;
    const float* wn = Whh + (size_t)(2*Hc + j) * Hc;

    for (int kc = 0; kc < Hc; kc += 128) {
        for (int i = tid; i < 1024; i += 256) {
            int r = i >> 5, kk = (i & 31) << 2;
            float4 v = make_float4(0,0,0,0);
            if (!first) v = *(const float4*)&y[((size_t)tprev*Bc + r)*(2*Hc) + dcol + kc + kk];
            *(float4*)&hs[r][kk] = v;
        }
        __syncthreads();
        #pragma unroll 8
        for (int k = 0; k < 128; k += 4) {
            float4 hv = *(const float4*)&hs[row][k];
            float4 w;
            w = *(const float4*)&wr[kc+k]; ar += hv.x*w.x + hv.y*w.y + hv.z*w.z + hv.w*w.w;
            w = *(const float4*)&wz[kc+k]; az += hv.x*w.x + hv.y*w.y + hv.z*w.z + hv.w*w.w;
            w = *(const float4*)&wn[kc+k]; an += hv.x*w.x + hv.y*w.y + hv.z*w.z + hv.w*w.w;
        }
        __syncthreads();
    }

    const float* g = gi + ((size_t)te*Bc + row) * G3;
    float gr = g[j], gz = g[Hc + j], gn = g[2*Hc + j];
    float hr = ar + bhh[j], hz = az + bhh[Hc + j], hn = an + bhh[2*Hc + j];
    float rg = 1.f / (1.f + __expf(-(gr + hr)));
    float zg = 1.f / (1.f + __expf(-(gz + hz)));
    float ng = tanhf(gn + rg * hn);
    float hp = first ? 0.f : y[((size_t)tprev*Bc + row)*(2*Hc) + dcol + j];
    y[((size_t)te*Bc + row)*(2*Hc) + dcol + j] = (1.f - zg)*ng + zg*hp;
}

// ---------------- enc_out = y1[:, :H] + y1[:, H:] ----------------
__global__ void combine_enc(const float* __restrict__ y1, float* __restrict__ eo)
{
    int i = blockIdx.x;
    int h = threadIdx.x * 4;
    float4 a = *(const float4*)&y1[(size_t)i*2*Hc + h];
    float4 b = *(const float4*)&y1[(size_t)i*2*Hc + Hc + h];
    float4 c = make_float4(a.x+b.x, a.y+b.y, a.z+b.z, a.w+b.w);
    *(float4*)&eo[(size_t)i*Hc + h] = c;
}

// ---------------- fused decoder GRU cell ----------------
__global__ __launch_bounds__(256) void dec_cell(
    const float* __restrict__ x,   const float* __restrict__ Wx, int ldx,
    const float* __restrict__ hin, const float* __restrict__ Whh,
    const float* __restrict__ pre, const float* __restrict__ bi,
    const float* __restrict__ bh,  float* __restrict__ hout)
{
    const int tid = threadIdx.x;
    const int row = tid & 31;
    const int j   = blockIdx.x * 8 + (tid >> 5);
    __shared__ float hs[32][136];
    float air=0.f, aiz=0.f, ain=0.f, ahr=0.f, ahz=0.f, ahn=0.f;
    const float* wxr = Wx + (size_t)j * ldx;
    const float* wxz = Wx + (size_t)(Hc  + j) * ldx;
    const float* wxn = Wx + (size_t)(2*Hc + j) * ldx;
    const float* whr = Whh + (size_t)j * Hc;
    const float* whz = Whh + (size_t)(Hc  + j) * Hc;
    const float* whn = Whh + (size_t)(2*Hc + j) * Hc;

    for (int kc = 0; kc < Hc; kc += 128) {
        for (int i = tid; i < 1024; i += 256) {
            int r = i >> 5, kk = (i & 31) << 2;
            *(float4*)&hs[r][kk] = *(const float4*)&x[(size_t)r*Hc + kc + kk];
        }
        __syncthreads();
        #pragma unroll 8
        for (int k = 0; k < 128; k += 4) {
            float4 hv = *(const float4*)&hs[row][k];
            float4 w;
            w = *(const float4*)&wxr[kc+k]; air += hv.x*w.x + hv.y*w.y + hv.z*w.z + hv.w*w.w;
            w = *(const float4*)&wxz[kc+k]; aiz += hv.x*w.x + hv.y*w.y + hv.z*w.z + hv.w*w.w;
            w = *(const float4*)&wxn[kc+k]; ain += hv.x*w.x + hv.y*w.y + hv.z*w.z + hv.w*w.w;
        }
        __syncthreads();
    }
    for (int kc = 0; kc < Hc; kc += 128) {
        for (int i = tid; i < 1024; i += 256) {
            int r = i >> 5, kk = (i & 31) << 2;
            *(float4*)&hs[r][kk] = *(const float4*)&hin[(size_t)r*Hc + kc + kk];
        }
        __syncthreads();
        #pragma unroll 8
        for (int k = 0; k < 128; k += 4) {
            float4 hv = *(const float4*)&hs[row][k];
            float4 w;
            w = *(const float4*)&whr[kc+k]; ahr += hv.x*w.x + hv.y*w.y + hv.z*w.z + hv.w*w.w;
            w = *(const float4*)&whz[kc+k]; ahz += hv.x*w.x + hv.y*w.y + hv.z*w.z + hv.w*w.w;
            w = *(const float4*)&whn[kc+k]; ahn += hv.x*w.x + hv.y*w.y + hv.z*w.z + hv.w*w.w;
        }
        __syncthreads();
    }

    float gir = air, giz = aiz, gin = ain;
    if (pre) { const float* p = pre + (size_t)row * G3; gir += p[j]; giz += p[Hc+j]; gin += p[2*Hc+j]; }
    if (bi)  { gir += bi[j]; giz += bi[Hc+j]; gin += bi[2*Hc+j]; }
    float ghr = ahr + bh[j], ghz = ahz + bh[Hc+j], ghn = ahn + bh[2*Hc+j];
    float rg = 1.f / (1.f + __expf(-(gir + ghr)));
    float zg = 1.f / (1.f + __expf(-(giz + ghz)));
    float ng = tanhf(gin + rg * ghn);
    hout[(size_t)row*Hc + j] = (1.f - zg)*ng + zg*hin[(size_t)row*Hc + j];
}

// ---------------- q = h1 @ Wd^T + bd ----------------
__global__ __launch_bounds__(256) void linear_q(
    const float* __restrict__ x, const float* __restrict__ Wd,
    const float* __restrict__ bd, float* __restrict__ q)
{
    const int tid = threadIdx.x;
    const int row = tid & 31;
    const int j   = blockIdx.x * 8 + (tid >> 5);
    __shared__ float hs[32][136];
    float acc = 0.f;
    const float* wj = Wd + (size_t)j * Hc;
    for (int kc = 0; kc < Hc; kc += 128) {
        for (int i = tid; i < 1024; i += 256) {
            int r = i >> 5, kk = (i & 31) << 2;
            *(float4*)&hs[r][kk] = *(const float4*)&x[(size_t)r*Hc + kc + kk];
        }
        __syncthreads();
        #pragma unroll 8
        for (int k = 0; k < 128; k += 4) {
            float4 hv = *(const float4*)&hs[row][k];
            float4 w  = *(const float4*)&wj[kc+k];
            acc += hv.x*w.x + hv.y*w.y + hv.z*w.z + hv.w*w.w;
        }
        __syncthreads();
    }
    q[(size_t)row*Hc + j] = acc + bd[j];
}

// ---------------- attention + feat emit ----------------
__global__ __launch_bounds__(256) void attn_step(
    const float* __restrict__ q, const float* __restrict__ encq,
    const float* __restrict__ encout, const float* __restrict__ h1,
    float* __restrict__ ctxout, float* __restrict__ feat)
{
    const int b = blockIdx.x, tid = threadIdx.x, lane = tid & 31, w = tid >> 5;
    __shared__ float qs[512];
    __shared__ float es[128];
    __shared__ float ssum[4];
    qs[tid] = q[(size_t)b*Hc + tid];
    qs[tid + 256] = q[(size_t)b*Hc + tid + 256];
    __syncthreads();

    for (int l = w; l < Lc; l += 8) {
        const float* eqr = encq + ((size_t)l*Bc + b) * Ac;
        float s = 0.f;
        #pragma unroll
        for (int qk = 0; qk < 4; qk++) {
            int k = qk*128 + lane*4;
            float4 a = *(const float4*)&eqr[k];
            float4 c = *(const float4*)&qs[k];
            s += a.x*c.x + a.y*c.y + a.z*c.z + a.w*c.w;
        }
        #pragma unroll
        for (int off = 16; off; off >>= 1) s += __shfl_xor_sync(0xffffffffu, s, off);
        if (lane == 0) es[l] = __expf(tanhf(s));
    }
    __syncthreads();
    if (tid < 128) {
        float v = es[tid];
        #pragma unroll
        for (int off = 16; off; off >>= 1) v += __shfl_xor_sync(0xffffffffu, v, off);
        if (lane == 0) ssum[tid >> 5] = v;
    }
    __syncthreads();
    float inv = 1.f / (ssum[0] + ssum[1] + ssum[2] + ssum[3]);

    float a0 = 0.f, a1 = 0.f;
    for (int l = 0; l < Lc; l++) {
        float wl = es[l];
        const float* eo = encout + ((size_t)l*Bc + b) * Hc;
        a0 += wl * eo[tid];
        a1 += wl * eo[tid + 256];
    }
    a0 *= inv; a1 *= inv;
    ctxout[(size_t)b*Hc + tid]       = a0;
    ctxout[(size_t)b*Hc + tid + 256] = a1;
    feat[(size_t)b*2*Hc + tid]             = h1[(size_t)b*Hc + tid];
    feat[(size_t)b*2*Hc + tid + 256]       = h1[(size_t)b*Hc + tid + 256];
    feat[(size_t)b*2*Hc + Hc + tid]        = a0;
    feat[(size_t)b*2*Hc + Hc + tid + 256]  = a1;
}

// ================================================================================
extern "C" void kernel_launch(void* const* d_in, const int* in_sizes, int n_in,
                              void* d_out, int out_size)
{
    const int*   src_tokens = (const int*)  d_in[0];
    const int*   trgt_seq   = (const int*)  d_in[1];
    const float* enc_embed  = (const float*)d_in[3];
    const float* enc_Wih0   = (const float*)d_in[4];
    const float* enc_Whh0   = (const float*)d_in[5];
    const float* enc_bih0   = (const float*)d_in[6];
    const float* enc_bhh0   = (const float*)d_in[7];
    const float* enc_Wih1   = (const float*)d_in[8];
    const float* enc_Whh1   = (const float*)d_in[9];
    const float* enc_bih1   = (const float*)d_in[10];
    const float* enc_bhh1   = (const float*)d_in[11];
    const float* dec_embed  = (const float*)d_in[12];
    const float* dec_Wih0   = (const float*)d_in[13];
    const float* dec_Whh0   = (const float*)d_in[14];
    const float* dec_bih0   = (const float*)d_in[15];
    const float* dec_bhh0   = (const float*)d_in[16];
    const float* dec_Wih1   = (const float*)d_in[17];
    const float* dec_Whh1   = (const float*)d_in[18];
    const float* dec_bih1   = (const float*)d_in[19];
    const float* dec_bhh1   = (const float*)d_in[20];
    const float* attn_We    = (const float*)d_in[21];
    const float* attn_be    = (const float*)d_in[22];
    const float* attn_Wd    = (const float*)d_in[23];
    const float* attn_bd    = (const float*)d_in[24];
    const float* mlp_W1     = (const float*)d_in[25];
    const float* mlp_b1     = (const float*)d_in[26];
    const float* mlp_W2     = (const float*)d_in[27];
    const float* mlp_b2     = (const float*)d_in[28];

    float *emb, *decemb, *gi, *y0, *y1, *eo, *eq, *dpre, *h0b, *h1b, *ctxb, *qb, *feat, *hid;
    __nv_bfloat16 *Ah, *Al, *Bh, *Bl;
    cudaGetSymbolAddress((void**)&emb,    d_emb);
    cudaGetSymbolAddress((void**)&decemb, d_decemb);
    cudaGetSymbolAddress((void**)&gi,     d_gi);
    cudaGetSymbolAddress((void**)&y0,     d_y0);
    cudaGetSymbolAddress((void**)&y1,     d_y1);
    cudaGetSymbolAddress((void**)&eo,     d_eo);
    cudaGetSymbolAddress((void**)&eq,     d_eq);
    cudaGetSymbolAddress((void**)&dpre,   d_dpre);
    cudaGetSymbolAddress((void**)&h0b,    d_h0b);
    cudaGetSymbolAddress((void**)&h1b,    d_h1b);
    cudaGetSymbolAddress((void**)&ctxb,   d_ctxb);
    cudaGetSymbolAddress((void**)&qb,     d_qb);
    cudaGetSymbolAddress((void**)&feat,   d_feat);
    cudaGetSymbolAddress((void**)&hid,    d_hid);
    cudaGetSymbolAddress((void**)&Ah,     d_Ah);
    cudaGetSymbolAddress((void**)&Al,     d_Al);
    cudaGetSymbolAddress((void**)&Bh,     d_Bh);
    cudaGetSymbolAddress((void**)&Bl,     d_Bl);

    cudaMemsetAsync(h0b,  0, Bc*Hc*sizeof(float));
    cudaMemsetAsync(h1b,  0, Bc*Hc*sizeof(float));
    cudaMemsetAsync(ctxb, 0, Bc*Hc*sizeof(float));

    // embeddings
    gather_rows<<<Lc*Bc, 128>>>(src_tokens, enc_embed, emb, 0);
    gather_rows<<<MBc,   128>>>(trgt_seq,   dec_embed, decemb, 1);

    // W2 split-bf16 conversion (input-only dependency; do it up front)
    {
        long n = (long)Vc * 1024;
        conv_split<<<(unsigned)((n + 255) / 256), 256>>>(mlp_W2, Bh, Bl, n, n);
    }

    // encoder layer0
    for (int d = 0; d < 2; d++)
        sgemm128<<<dim3(G3/128, (Lc*Bc)/128), 256>>>(Lc*Bc, G3, Ec,
            emb, Ec, enc_Wih0 + (size_t)d*G3*Ec, Ec, enc_bih0 + d*G3,
            gi + (size_t)d*Lc*Bc*G3, G3, 0);
    for (int s = 0; s < Lc; s++)
        gru_step<<<dim3(64, 2), 256>>>(gi, enc_Whh0, enc_bhh0, y0, s);

    // encoder layer1
    for (int d = 0; d < 2; d++)
        sgemm128<<<dim3(G3/128, (Lc*Bc)/128), 256>>>(Lc*Bc, G3, 2*Hc,
            y0, 2*Hc, enc_Wih1 + (size_t)d*G3*2*Hc, 2*Hc, enc_bih1 + d*G3,
            gi + (size_t)d*Lc*Bc*G3, G3, 0);
    for (int s = 0; s < Lc; s++)
        gru_step<<<dim3(64, 2), 256>>>(gi, enc_Whh1, enc_bhh1, y1, s);

    combine_enc<<<Lc*Bc, 128>>>(y1, eo);

    sgemm128<<<dim3(Ac/128, (Lc*Bc)/128), 256>>>(Lc*Bc, Ac, Hc,
        eo, Hc, attn_We, Hc, attn_be, eq, Ac, 0);

    sgemm128<<<dim3(G3/128, (MBc+127)/128), 256>>>(MBc, G3, Ec,
        decemb, Ec, dec_Wih0, Ec + Hc, dec_bih0, dpre, G3, 0);

    for (int t = 0; t < TDc; t++) {
        int r = t & 1, wix = 1 - r;
        dec_cell<<<64, 256>>>(ctxb + (size_t)r*Bc*Hc, dec_Wih0 + Hc, Ec + Hc,
                              h0b + (size_t)r*Bc*Hc, dec_Whh0,
                              dpre + (size_t)t*Bc*G3, nullptr, dec_bhh0,
                              h0b + (size_t)wix*Bc*Hc);
        dec_cell<<<64, 256>>>(h0b + (size_t)wix*Bc*Hc, dec_Wih1, Hc,
                              h1b + (size_t)r*Bc*Hc, dec_Whh1,
                              nullptr, dec_bih1, dec_bhh1,
                              h1b + (size_t)wix*Bc*Hc);
        linear_q<<<64, 256>>>(h1b + (size_t)wix*Bc*Hc, attn_Wd, attn_bd, qb);
        attn_step<<<Bc, 256>>>(qb, eq, eo, h1b + (size_t)wix*Bc*Hc,
                               ctxb + (size_t)wix*Bc*Hc, feat + (size_t)t*Bc*2*Hc);
    }

    // MLP1 (fp32 SIMT), then split-bf16 conversion of hid (pad 2016 -> 2048 rows)
    sgemm128<<<dim3((2*Hc)/128, (MBc+127)/128), 256>>>(MBc, 2*Hc, 2*Hc,
        feat, 2*Hc, mlp_W1, 2*Hc, mlp_b1, hid, 2*Hc, 1 /*relu*/);
    {
        long nv = (long)MBc * 1024, nt = (long)MPAD * 1024;
        conv_split<<<(unsigned)((nt + 255) / 256), 256>>>(hid, Ah, Al, nv, nt);
    }

    // MLP2 on mma.sync bf16 tensor cores (split-bf16, fp32 accumulate)
    mma_logits<<<dim3(Vc/128, MPAD/128), 256>>>(Ah, Al, Bh, Bl, mlp_b2, (float*)d_out);
}

// round 7
// speedup vs baseline: 1.1742x; 1.0841x over previous
#include <cuda_runtime.h>
#include <cuda_bf16.h>
#include <cstdint>
#include <math.h>

#define Lc 128
#define Bc 32
#define Tc 64
#define TDc 63
#define Ec 512
#define Hc 512
#define Ac 512
#define Vc 32000
#define G3 1536
#define MBc (TDc*Bc)   // 2016
#define MPAD 2048

// ---------------- scratch ----------------
__device__ float d_emb   [Lc*Bc*Ec];
__device__ float d_decemb[MBc*Ec];
__device__ float d_gi    [Lc*Bc*2*G3];       // [4096][3072]: dir0 cols 0:1536, dir1 1536:3072
__device__ float d_y0    [Lc*Bc*2*Hc];
__device__ float d_y1    [Lc*Bc*2*Hc];
__device__ float d_eo    [Lc*Bc*Hc];
__device__ float d_eq    [Lc*Bc*Ac];
__device__ float d_dpre  [MPAD*G3];
__device__ float d_h0b   [2*Bc*Hc];
__device__ float d_h1b   [2*Bc*Hc];
__device__ float d_ctxb  [2*Bc*Hc];
__device__ float d_qb    [Bc*Ac];
__device__ float d_feat  [MBc*2*Hc];
// bf16 split operand buffers
__device__ __nv_bfloat16 d_Ah[4096*1024];
__device__ __nv_bfloat16 d_Al[4096*1024];
__device__ __nv_bfloat16 d_Wh[3072*1024];
__device__ __nv_bfloat16 d_Wl[3072*1024];
__device__ __nv_bfloat16 d_Bh[(size_t)Vc*1024];
__device__ __nv_bfloat16 d_Bl[(size_t)Vc*1024];

// ---------------- embedding gathers ----------------
__global__ void gather_rows(const int* __restrict__ tok, const float* __restrict__ tab,
                            float* __restrict__ out, int mode)
{
    int row = blockIdx.x;
    int idx;
    if (mode == 0) idx = tok[row];
    else { int t = row >> 5, b = row & 31; idx = tok[b*Tc + t]; }
    const float4* src = (const float4*)(tab + (size_t)idx * Ec);
    float4* dst = (float4*)(out + (size_t)row * Ec);
    dst[threadIdx.x] = src[threadIdx.x];
}

// ---------------- fp32 -> split bf16 (linear, zero-padded tail) ----------------
__global__ void conv_split(const float* __restrict__ in, __nv_bfloat16* __restrict__ hi,
                           __nv_bfloat16* __restrict__ lo, long n_valid, long n_total)
{
    long i = (long)blockIdx.x * blockDim.x + threadIdx.x;
    if (i >= n_total) return;
    float v = (i < n_valid) ? in[i] : 0.f;
    __nv_bfloat16 h = __float2bfloat16(v);
    hi[i] = h;
    lo[i] = __float2bfloat16(v - __bfloat162float(h));
}

// ---------------- strided fp32 -> split bf16 (packs [rows x cols] from ld-strided src) ----
__global__ void conv_split2d(const float* __restrict__ in, int ld, int rows, int cols,
                             __nv_bfloat16* __restrict__ hi, __nv_bfloat16* __restrict__ lo)
{
    long i = (long)blockIdx.x * blockDim.x + threadIdx.x;
    if (i >= (long)rows * cols) return;
    int r = (int)(i / cols), c = (int)(i % cols);
    float v = in[(size_t)r * ld + c];
    __nv_bfloat16 h = __float2bfloat16(v);
    hi[i] = h;
    lo[i] = __float2bfloat16(v - __bfloat162float(h));
}

// =============== generic split-bf16 tensor GEMM: C = A @ B^T (+bias, epilogue) ===============
// 3-term split: D += Ah*Bh + Ah*Bl + Al*Bh (fp32 accum). Tile 128x128, BK=32, 2-stage cp.async.
// flags: bit0 relu, bit1 remap rows (m -> (m&31)*63+(m>>5)) + guard m<MBc, bit2 split-bf16 output
#define F_RELU  1
#define F_REMAP 2
#define F_SPLIT 4
#define SLDA 40
#define TILEB (128*SLDA*2)          // bytes per operand tile
#define STAGEB (4*TILEB)            // 4 operand tiles per stage
#define GEMM_SMEM (2*STAGEB)        // 2 stages = 81920 B

__device__ __forceinline__ uint32_t smem_u32(const void* p) {
    uint32_t a;
    asm("{ .reg .u64 t; cvta.to.shared.u64 t, %1; cvt.u32.u64 %0, t; }" : "=r"(a) : "l"(p));
    return a;
}
__device__ __forceinline__ void ldm4(uint32_t& r0, uint32_t& r1, uint32_t& r2, uint32_t& r3, uint32_t a) {
    asm volatile("ldmatrix.sync.aligned.m8n8.x4.shared.b16 {%0,%1,%2,%3}, [%4];"
                 : "=r"(r0), "=r"(r1), "=r"(r2), "=r"(r3) : "r"(a));
}
__device__ __forceinline__ void mma16816(float* c, const uint32_t* a, const uint32_t* b) {
    asm volatile("mma.sync.aligned.m16n8k16.row.col.f32.bf16.bf16.f32 "
                 "{%0,%1,%2,%3},{%4,%5,%6,%7},{%8,%9},{%0,%1,%2,%3};"
                 : "+f"(c[0]), "+f"(c[1]), "+f"(c[2]), "+f"(c[3])
                 : "r"(a[0]), "r"(a[1]), "r"(a[2]), "r"(a[3]), "r"(b[0]), "r"(b[1]));
}
#define CP16(dst, src) asm volatile("cp.async.cg.shared.global [%0], [%1], 16;" :: "r"(dst), "l"(src))
#define CP_COMMIT()    asm volatile("cp.async.commit_group;" ::: "memory")
#define CP_WAIT1()     asm volatile("cp.async.wait_group 1;" ::: "memory")

__global__ __launch_bounds__(256) void gemm_bf16(
    int K,
    const __nv_bfloat16* __restrict__ Ah, const __nv_bfloat16* __restrict__ Al,
    const __nv_bfloat16* __restrict__ Bh, const __nv_bfloat16* __restrict__ Bl,
    const float* __restrict__ bias,
    float* __restrict__ Cf, __nv_bfloat16* __restrict__ Chi, __nv_bfloat16* __restrict__ Clo,
    int ldc, int flags)
{
    extern __shared__ char smem[];
    const uint32_t smem_base = smem_u32(smem);
    const int tid = threadIdx.x, wid = tid >> 5, lane = tid & 31;
    const int nBase = blockIdx.x * 128;
    const int mBase = blockIdx.y * 128;
    const int warpM = (wid & 1) * 64;
    const int warpN = (wid >> 1) * 32;

    const __nv_bfloat16* g[4] = {
        Ah + (size_t)mBase * K, Al + (size_t)mBase * K,
        Bh + (size_t)nBase * K, Bl + (size_t)nBase * K };

    // per-thread load mapping: 2 int4 segs per tile (512 segs / 256 thr)
    const int lRow0 = tid >> 2, lSc0 = (tid & 3);
    const int lRow1 = (tid + 256) >> 2, lSc1 = ((tid + 256) & 3);

    // prefetch a stage
    auto prefetch = [&](int st, int kc) {
        #pragma unroll
        for (int op = 0; op < 4; op++) {
            uint32_t sb = smem_base + st * STAGEB + op * TILEB;
            CP16(sb + (uint32_t)(lRow0 * SLDA + lSc0 * 8) * 2, g[op] + (size_t)lRow0 * K + kc + lSc0 * 8);
            CP16(sb + (uint32_t)(lRow1 * SLDA + lSc1 * 8) * 2, g[op] + (size_t)lRow1 * K + kc + lSc1 * 8);
        }
    };

    float acc[4][4][4];
    #pragma unroll
    for (int i = 0; i < 4; i++)
        #pragma unroll
        for (int j = 0; j < 4; j++)
            #pragma unroll
            for (int e = 0; e < 4; e++) acc[i][j][e] = 0.f;

    const int aRow = (lane & 15), aK = (lane >> 4) * 8;
    const int bRow = ((lane >> 4) << 3) + (lane & 7), bK = ((lane >> 3) & 1) * 8;

    const int nch = K >> 5;
    prefetch(0, 0);
    CP_COMMIT();

    for (int c = 0; c < nch; c++) {
        if (c + 1 < nch) prefetch((c + 1) & 1, (c + 1) << 5);
        CP_COMMIT();
        CP_WAIT1();
        __syncthreads();

        const uint32_t stb = smem_base + (c & 1) * STAGEB;
        const uint32_t bAh = stb, bAl = stb + TILEB, bBh = stb + 2*TILEB, bBl = stb + 3*TILEB;

        #pragma unroll
        for (int ks = 0; ks < 2; ks++) {
            const int kb = ks * 16;
            uint32_t fbh[4][2], fbl[4][2];
            #pragma unroll
            for (int nt = 0; nt < 2; nt++) {
                uint32_t off = ((uint32_t)(warpN + nt * 16 + bRow) * SLDA + kb + bK) * 2;
                ldm4(fbh[nt*2][0], fbh[nt*2][1], fbh[nt*2+1][0], fbh[nt*2+1][1], bBh + off);
                ldm4(fbl[nt*2][0], fbl[nt*2][1], fbl[nt*2+1][0], fbl[nt*2+1][1], bBl + off);
            }
            #pragma unroll
            for (int mi = 0; mi < 4; mi++) {
                uint32_t fah[4], fal[4];
                uint32_t off = ((uint32_t)(warpM + mi * 16 + aRow) * SLDA + kb + aK) * 2;
                ldm4(fah[0], fah[1], fah[2], fah[3], bAh + off);
                ldm4(fal[0], fal[1], fal[2], fal[3], bAl + off);
                #pragma unroll
                for (int ni = 0; ni < 4; ni++) {
                    mma16816(acc[mi][ni], fah, fbh[ni]);
                    mma16816(acc[mi][ni], fah, fbl[ni]);
                    mma16816(acc[mi][ni], fal, fbh[ni]);
                }
            }
        }
        __syncthreads();
    }

    // epilogue
    const int mLane = lane >> 2;
    const int nLane = (lane & 3) * 2;
    #pragma unroll
    for (int mi = 0; mi < 4; mi++) {
        #pragma unroll
        for (int half = 0; half < 2; half++) {
            int m = mBase + warpM + mi * 16 + mLane + half * 8;
            int orow = m;
            if (flags & F_REMAP) {
                if (m >= MBc) continue;
                orow = (m & 31) * TDc + (m >> 5);
            }
            #pragma unroll
            for (int ni = 0; ni < 4; ni++) {
                int n = nBase + warpN + ni * 8 + nLane;
                float vx = acc[mi][ni][half * 2 + 0] + bias[n];
                float vy = acc[mi][ni][half * 2 + 1] + bias[n + 1];
                if (flags & F_RELU) { vx = fmaxf(vx, 0.f); vy = fmaxf(vy, 0.f); }
                if (flags & F_SPLIT) {
                    size_t o = (size_t)orow * ldc + n;
                    __nv_bfloat16 hx = __float2bfloat16(vx), hy = __float2bfloat16(vy);
                    Chi[o] = hx; Chi[o+1] = hy;
                    Clo[o]   = __float2bfloat16(vx - __bfloat162float(hx));
                    Clo[o+1] = __float2bfloat16(vy - __bfloat162float(hy));
                } else {
                    *(float2*)(Cf + (size_t)orow * ldc + n) = make_float2(vx, vy);
                }
            }
        }
    }
}

// ---------------- fused encoder GRU recurrent step (gi stride 3072) ----------------
__global__ __launch_bounds__(256) void gru_step(
    const float* __restrict__ giBase, const float* __restrict__ WhhBase,
    const float* __restrict__ bhhBase, float* __restrict__ y, int s)
{
    const int dir = blockIdx.y;
    const int tid = threadIdx.x;
    const int row = tid & 31;
    const int j   = blockIdx.x * 8 + (tid >> 5);
    const int te    = dir ? (Lc - 1 - s) : s;
    const int tprev = dir ? (te + 1) : (te - 1);
    const bool first = (s == 0);
    const int dcol = dir * Hc;
    const float* Whh = WhhBase + (size_t)dir * G3 * Hc;
    const float* bhh = bhhBase + dir * G3;

    __shared__ float hs[32][136];
    float ar = 0.f, az = 0.f, an = 0.f;
    const float* wr = Whh + (size_t)j * Hc;
    const float* wz = Whh + (size_t)(Hc  + j) * Hc;
    const float* wn = Whh + (size_t)(2*Hc + j) * Hc;

    for (int kc = 0; kc < Hc; kc += 128) {
        for (int i = tid; i < 1024; i += 256) {
            int r = i >> 5, kk = (i & 31) << 2;
            float4 v = make_float4(0,0,0,0);
            if (!first) v = *(const float4*)&y[((size_t)tprev*Bc + r)*(2*Hc) + dcol + kc + kk];
            *(float4*)&hs[r][kk] = v;
        }
        __syncthreads();
        #pragma unroll 8
        for (int k = 0; k < 128; k += 4) {
            float4 hv = *(const float4*)&hs[row][k];
            float4 w;
            w = *(const float4*)&wr[kc+k]; ar += hv.x*w.x + hv.y*w.y + hv.z*w.z + hv.w*w.w;
            w = *(const float4*)&wz[kc+k]; az += hv.x*w.x + hv.y*w.y + hv.z*w.z + hv.w*w.w;
            w = *(const float4*)&wn[kc+k]; an += hv.x*w.x + hv.y*w.y + hv.z*w.z + hv.w*w.w;
        }
        __syncthreads();
    }

    const float* gp = giBase + ((size_t)te*Bc + row) * (2*G3) + dir * G3;
    float gr = gp[j], gz = gp[Hc + j], gn = gp[2*Hc + j];
    float hr = ar + bhh[j], hz = az + bhh[Hc + j], hn = an + bhh[2*Hc + j];
    float rg = 1.f / (1.f + __expf(-(gr + hr)));
    float zg = 1.f / (1.f + __expf(-(gz + hz)));
    float ng = tanhf(gn + rg * hn);
    float hp = first ? 0.f : y[((size_t)tprev*Bc + row)*(2*Hc) + dcol + j];
    y[((size_t)te*Bc + row)*(2*Hc) + dcol + j] = (1.f - zg)*ng + zg*hp;
}

// ---------------- enc_out = y1[:, :H] + y1[:, H:] ----------------
__global__ void combine_enc(const float* __restrict__ y1, float* __restrict__ eo)
{
    int i = blockIdx.x;
    int h = threadIdx.x * 4;
    float4 a = *(const float4*)&y1[(size_t)i*2*Hc + h];
    float4 b = *(const float4*)&y1[(size_t)i*2*Hc + Hc + h];
    *(float4*)&eo[(size_t)i*Hc + h] = make_float4(a.x+b.x, a.y+b.y, a.z+b.z, a.w+b.w);
}

// ---------------- fused decoder GRU cell ----------------
__global__ __launch_bounds__(256) void dec_cell(
    const float* __restrict__ x,   const float* __restrict__ Wx, int ldx,
    const float* __restrict__ hin, const float* __restrict__ Whh,
    const float* __restrict__ pre, const float* __restrict__ bi,
    const float* __restrict__ bh,  float* __restrict__ hout)
{
    const int tid = threadIdx.x;
    const int row = tid & 31;
    const int j   = blockIdx.x * 8 + (tid >> 5);
    __shared__ float hs[32][136];
    float air=0.f, aiz=0.f, ain=0.f, ahr=0.f, ahz=0.f, ahn=0.f;
    const float* wxr = Wx + (size_t)j * ldx;
    const float* wxz = Wx + (size_t)(Hc  + j) * ldx;
    const float* wxn = Wx + (size_t)(2*Hc + j) * ldx;
    const float* whr = Whh + (size_t)j * Hc;
    const float* whz = Whh + (size_t)(Hc  + j) * Hc;
    const float* whn = Whh + (size_t)(2*Hc + j) * Hc;

    for (int kc = 0; kc < Hc; kc += 128) {
        for (int i = tid; i < 1024; i += 256) {
            int r = i >> 5, kk = (i & 31) << 2;
            *(float4*)&hs[r][kk] = *(const float4*)&x[(size_t)r*Hc + kc + kk];
        }
        __syncthreads();
        #pragma unroll 8
        for (int k = 0; k < 128; k += 4) {
            float4 hv = *(const float4*)&hs[row][k];
            float4 w;
            w = *(const float4*)&wxr[kc+k]; air += hv.x*w.x + hv.y*w.y + hv.z*w.z + hv.w*w.w;
            w = *(const float4*)&wxz[kc+k]; aiz += hv.x*w.x + hv.y*w.y + hv.z*w.z + hv.w*w.w;
            w = *(const float4*)&wxn[kc+k]; ain += hv.x*w.x + hv.y*w.y + hv.z*w.z + hv.w*w.w;
        }
        __syncthreads();
    }
    for (int kc = 0; kc < Hc; kc += 128) {
        for (int i = tid; i < 1024; i += 256) {
            int r = i >> 5, kk = (i & 31) << 2;
            *(float4*)&hs[r][kk] = *(const float4*)&hin[(size_t)r*Hc + kc + kk];
        }
        __syncthreads();
        #pragma unroll 8
        for (int k = 0; k < 128; k += 4) {
            float4 hv = *(const float4*)&hs[row][k];
            float4 w;
            w = *(const float4*)&whr[kc+k]; ahr += hv.x*w.x + hv.y*w.y + hv.z*w.z + hv.w*w.w;
            w = *(const float4*)&whz[kc+k]; ahz += hv.x*w.x + hv.y*w.y + hv.z*w.z + hv.w*w.w;
            w = *(const float4*)&whn[kc+k]; ahn += hv.x*w.x + hv.y*w.y + hv.z*w.z + hv.w*w.w;
        }
        __syncthreads();
    }

    float gir = air, giz = aiz, gin = ain;
    if (pre) { const float* p = pre + (size_t)row * G3; gir += p[j]; giz += p[Hc+j]; gin += p[2*Hc+j]; }
    if (bi)  { gir += bi[j]; giz += bi[Hc+j]; gin += bi[2*Hc+j]; }
    float ghr = ahr + bh[j], ghz = ahz + bh[Hc+j], ghn = ahn + bh[2*Hc+j];
    float rg = 1.f / (1.f + __expf(-(gir + ghr)));
    float zg = 1.f / (1.f + __expf(-(giz + ghz)));
    float ng = tanhf(gin + rg * ghn);
    hout[(size_t)row*Hc + j] = (1.f - zg)*ng + zg*hin[(size_t)row*Hc + j];
}

// ---------------- q = h1 @ Wd^T + bd ----------------
__global__ __launch_bounds__(256) void linear_q(
    const float* __restrict__ x, const float* __restrict__ Wd,
    const float* __restrict__ bd, float* __restrict__ q)
{
    const int tid = threadIdx.x;
    const int row = tid & 31;
    const int j   = blockIdx.x * 8 + (tid >> 5);
    __shared__ float hs[32][136];
    float acc = 0.f;
    const float* wj = Wd + (size_t)j * Hc;
    for (int kc = 0; kc < Hc; kc += 128) {
        for (int i = tid; i < 1024; i += 256) {
            int r = i >> 5, kk = (i & 31) << 2;
            *(float4*)&hs[r][kk] = *(const float4*)&x[(size_t)r*Hc + kc + kk];
        }
        __syncthreads();
        #pragma unroll 8
        for (int k = 0; k < 128; k += 4) {
            float4 hv = *(const float4*)&hs[row][k];
            float4 w  = *(const float4*)&wj[kc+k];
            acc += hv.x*w.x + hv.y*w.y + hv.z*w.z + hv.w*w.w;
        }
        __syncthreads();
    }
    q[(size_t)row*Hc + j] = acc + bd[j];
}

// ---------------- attention + feat emit ----------------
__global__ __launch_bounds__(256) void attn_step(
    const float* __restrict__ q, const float* __restrict__ encq,
    const float* __restrict__ encout, const float* __restrict__ h1,
    float* __restrict__ ctxout, float* __restrict__ feat)
{
    const int b = blockIdx.x, tid = threadIdx.x, lane = tid & 31, w = tid >> 5;
    __shared__ float qs[512];
    __shared__ float es[128];
    __shared__ float ssum[4];
    qs[tid] = q[(size_t)b*Hc + tid];
    qs[tid + 256] = q[(size_t)b*Hc + tid + 256];
    __syncthreads();

    for (int l = w; l < Lc; l += 8) {
        const float* eqr = encq + ((size_t)l*Bc + b) * Ac;
        float s = 0.f;
        #pragma unroll
        for (int qk = 0; qk < 4; qk++) {
            int k = qk*128 + lane*4;
            float4 a = *(const float4*)&eqr[k];
            float4 c = *(const float4*)&qs[k];
            s += a.x*c.x + a.y*c.y + a.z*c.z + a.w*c.w;
        }
        #pragma unroll
        for (int off = 16; off; off >>= 1) s += __shfl_xor_sync(0xffffffffu, s, off);
        if (lane == 0) es[l] = __expf(tanhf(s));
    }
    __syncthreads();
    if (tid < 128) {
        float v = es[tid];
        #pragma unroll
        for (int off = 16; off; off >>= 1) v += __shfl_xor_sync(0xffffffffu, v, off);
        if (lane == 0) ssum[tid >> 5] = v;
    }
    __syncthreads();
    float inv = 1.f / (ssum[0] + ssum[1] + ssum[2] + ssum[3]);

    float a0 = 0.f, a1 = 0.f;
    for (int l = 0; l < Lc; l++) {
        float wl = es[l];
        const float* eo = encout + ((size_t)l*Bc + b) * Hc;
        a0 += wl * eo[tid];
        a1 += wl * eo[tid + 256];
    }
    a0 *= inv; a1 *= inv;
    ctxout[(size_t)b*Hc + tid]       = a0;
    ctxout[(size_t)b*Hc + tid + 256] = a1;
    feat[(size_t)b*2*Hc + tid]             = h1[(size_t)b*Hc + tid];
    feat[(size_t)b*2*Hc + tid + 256]       = h1[(size_t)b*Hc + tid + 256];
    feat[(size_t)b*2*Hc + Hc + tid]        = a0;
    feat[(size_t)b*2*Hc + Hc + tid + 256]  = a1;
}

// ================================================================================
extern "C" void kernel_launch(void* const* d_in, const int* in_sizes, int n_in,
                              void* d_out, int out_size)
{
    const int*   src_tokens = (const int*)  d_in[0];
    const int*   trgt_seq   = (const int*)  d_in[1];
    const float* enc_embed  = (const float*)d_in[3];
    const float* enc_Wih0   = (const float*)d_in[4];
    const float* enc_Whh0   = (const float*)d_in[5];
    const float* enc_bih0   = (const float*)d_in[6];
    const float* enc_bhh0   = (const float*)d_in[7];
    const float* enc_Wih1   = (const float*)d_in[8];
    const float* enc_Whh1   = (const float*)d_in[9];
    const float* enc_bih1   = (const float*)d_in[10];
    const float* enc_bhh1   = (const float*)d_in[11];
    const float* dec_embed  = (const float*)d_in[12];
    const float* dec_Wih0   = (const float*)d_in[13];
    const float* dec_Whh0   = (const float*)d_in[14];
    const float* dec_bih0   = (const float*)d_in[15];
    const float* dec_bhh0   = (const float*)d_in[16];
    const float* dec_Wih1   = (const float*)d_in[17];
    const float* dec_Whh1   = (const float*)d_in[18];
    const float* dec_bih1   = (const float*)d_in[19];
    const float* dec_bhh1   = (const float*)d_in[20];
    const float* attn_We    = (const float*)d_in[21];
    const float* attn_be    = (const float*)d_in[22];
    const float* attn_Wd    = (const float*)d_in[23];
    const float* attn_bd    = (const float*)d_in[24];
    const float* mlp_W1     = (const float*)d_in[25];
    const float* mlp_b1     = (const float*)d_in[26];
    const float* mlp_W2     = (const float*)d_in[27];
    const float* mlp_b2     = (const float*)d_in[28];

    float *emb, *decemb, *gi, *y0, *y1, *eo, *eq, *dpre, *h0b, *h1b, *ctxb, *qb, *feat;
    __nv_bfloat16 *Ah, *Al, *Wh, *Wl, *Bh, *Bl;
    cudaGetSymbolAddress((void**)&emb,    d_emb);
    cudaGetSymbolAddress((void**)&decemb, d_decemb);
    cudaGetSymbolAddress((void**)&gi,     d_gi);
    cudaGetSymbolAddress((void**)&y0,     d_y0);
    cudaGetSymbolAddress((void**)&y1,     d_y1);
    cudaGetSymbolAddress((void**)&eo,     d_eo);
    cudaGetSymbolAddress((void**)&eq,     d_eq);
    cudaGetSymbolAddress((void**)&dpre,   d_dpre);
    cudaGetSymbolAddress((void**)&h0b,    d_h0b);
    cudaGetSymbolAddress((void**)&h1b,    d_h1b);
    cudaGetSymbolAddress((void**)&ctxb,   d_ctxb);
    cudaGetSymbolAddress((void**)&qb,     d_qb);
    cudaGetSymbolAddress((void**)&feat,   d_feat);
    cudaGetSymbolAddress((void**)&Ah,     d_Ah);
    cudaGetSymbolAddress((void**)&Al,     d_Al);
    cudaGetSymbolAddress((void**)&Wh,     d_Wh);
    cudaGetSymbolAddress((void**)&Wl,     d_Wl);
    cudaGetSymbolAddress((void**)&Bh,     d_Bh);
    cudaGetSymbolAddress((void**)&Bl,     d_Bl);

    cudaFuncSetAttribute(gemm_bf16, cudaFuncAttributeMaxDynamicSharedMemorySize, GEMM_SMEM);

    cudaMemsetAsync(h0b,  0, Bc*Hc*sizeof(float));
    cudaMemsetAsync(h1b,  0, Bc*Hc*sizeof(float));
    cudaMemsetAsync(ctxb, 0, Bc*Hc*sizeof(float));

    // embeddings
    gather_rows<<<Lc*Bc, 128>>>(src_tokens, enc_embed, emb, 0);
    gather_rows<<<MBc,   128>>>(trgt_seq,   dec_embed, decemb, 1);

    // mlp_W2 conversion (constant input; once per launch)
    { long n = (long)Vc * 1024; conv_split<<<(unsigned)(n/256), 256>>>(mlp_W2, Bh, Bl, n, n); }

    // ===== encoder layer0 pre: gi[4096][3072] = emb @ [Wih0_f; Wih0_b]^T + bih =====
    { long n = (long)Lc*Bc*Ec;  conv_split<<<(unsigned)(n/256), 256>>>(emb, Ah, Al, n, n); }
    { long n = (long)2*G3*Ec;   conv_split<<<(unsigned)(n/256), 256>>>(enc_Wih0, Wh, Wl, n, n); }
    gemm_bf16<<<dim3(2*G3/128, Lc*Bc/128), 256, GEMM_SMEM>>>(
        Ec, Ah, Al, Wh, Wl, enc_bih0, gi, nullptr, nullptr, 2*G3, 0);
    for (int s = 0; s < Lc; s++)
        gru_step<<<dim3(64, 2), 256>>>(gi, enc_Whh0, enc_bhh0, y0, s);

    // ===== encoder layer1 pre =====
    { long n = (long)Lc*Bc*2*Hc; conv_split<<<(unsigned)(n/256), 256>>>(y0, Ah, Al, n, n); }
    { long n = (long)2*G3*2*Hc;  conv_split<<<(unsigned)(n/256), 256>>>(enc_Wih1, Wh, Wl, n, n); }
    gemm_bf16<<<dim3(2*G3/128, Lc*Bc/128), 256, GEMM_SMEM>>>(
        2*Hc, Ah, Al, Wh, Wl, enc_bih1, gi, nullptr, nullptr, 2*G3, 0);
    for (int s = 0; s < Lc; s++)
        gru_step<<<dim3(64, 2), 256>>>(gi, enc_Whh1, enc_bhh1, y1, s);

    combine_enc<<<Lc*Bc, 128>>>(y1, eo);

    // ===== enc_q = eo @ We^T + be =====
    { long n = (long)Lc*Bc*Hc; conv_split<<<(unsigned)(n/256), 256>>>(eo, Ah, Al, n, n); }
    { long n = (long)Ac*Hc;    conv_split<<<(unsigned)(n/256), 256>>>(attn_We, Wh, Wl, n, n); }
    gemm_bf16<<<dim3(Ac/128, Lc*Bc/128), 256, GEMM_SMEM>>>(
        Hc, Ah, Al, Wh, Wl, attn_be, eq, nullptr, nullptr, Ac, 0);

    // ===== decoder pre: dpre = decemb @ Wih0[:, :E]^T + bih0 =====
    { long nv = (long)MBc*Ec, nt = (long)MPAD*Ec;
      conv_split<<<(unsigned)(nt/256), 256>>>(decemb, Ah, Al, nv, nt); }
    { long n = (long)G3*Ec;
      conv_split2d<<<(unsigned)(n/256), 256>>>(dec_Wih0, Ec + Hc, G3, Ec, Wh, Wl); }
    gemm_bf16<<<dim3(G3/128, MPAD/128), 256, GEMM_SMEM>>>(
        Ec, Ah, Al, Wh, Wl, dec_bih0, dpre, nullptr, nullptr, G3, 0);

    // ===== decoder recurrence (unchanged) =====
    for (int t = 0; t < TDc; t++) {
        int r = t & 1, wix = 1 - r;
        dec_cell<<<64, 256>>>(ctxb + (size_t)r*Bc*Hc, dec_Wih0 + Hc, Ec + Hc,
                              h0b + (size_t)r*Bc*Hc, dec_Whh0,
                              dpre + (size_t)t*Bc*G3, nullptr, dec_bhh0,
                              h0b + (size_t)wix*Bc*Hc);
        dec_cell<<<64, 256>>>(h0b + (size_t)wix*Bc*Hc, dec_Wih1, Hc,
                              h1b + (size_t)r*Bc*Hc, dec_Whh1,
                              nullptr, dec_bih1, dec_bhh1,
                              h1b + (size_t)wix*Bc*Hc);
        linear_q<<<64, 256>>>(h1b + (size_t)wix*Bc*Hc, attn_Wd, attn_bd, qb);
        attn_step<<<Bc, 256>>>(qb, eq, eo, h1b + (size_t)wix*Bc*Hc,
                               ctxb + (size_t)wix*Bc*Hc, feat + (size_t)t*Bc*2*Hc);
    }

    // ===== MLP1: hid = relu(feat @ W1^T + b1), emitted directly as split-bf16 =====
    { long nv = (long)MBc*2*Hc, nt = (long)MPAD*2*Hc;
      conv_split<<<(unsigned)(nt/256), 256>>>(feat, Ah, Al, nv, nt); }
    { long n = (long)2*Hc*2*Hc; conv_split<<<(unsigned)(n/256), 256>>>(mlp_W1, Wh, Wl, n, n); }
    __nv_bfloat16* Ah2 = Ah + (size_t)MPAD * 1024;
    __nv_bfloat16* Al2 = Al + (size_t)MPAD * 1024;
    gemm_bf16<<<dim3(2*Hc/128, MPAD/128), 256, GEMM_SMEM>>>(
        2*Hc, Ah, Al, Wh, Wl, mlp_b1, nullptr, Ah2, Al2, 2*Hc, F_RELU | F_SPLIT);

    // ===== MLP2 logits: out = remap(hid @ W2^T) + b2 =====
    gemm_bf16<<<dim3(Vc/128, MPAD/128), 256, GEMM_SMEM>>>(
        2*Hc, Ah2, Al2, Bh, Bl, mlp_b2, (float*)d_out, nullptr, nullptr, Vc, F_REMAP);
}

// round 9
// speedup vs baseline: 1.6571x; 1.4112x over previous
#include <cuda_runtime.h>
#include <cuda_bf16.h>
#include <cstdint>
#include <math.h>

#define Lc 128
#define Bc 32
#define Tc 64
#define TDc 63
#define Ec 512
#define Hc 512
#define Ac 512
#define Vc 32000
#define G3 1536
#define MBc (TDc*Bc)   // 2016
#define MPAD 2048

// ---------------- scratch ----------------
__device__ float d_emb   [Lc*Bc*Ec];
__device__ float d_decemb[MBc*Ec];
__device__ float d_gi    [Lc*Bc*2*G3];
__device__ float d_y0    [Lc*Bc*2*Hc];
__device__ float d_y1    [Lc*Bc*2*Hc];
__device__ float d_eo    [Lc*Bc*Hc];
__device__ float d_eq    [Lc*Bc*Ac];
__device__ float d_dpre  [MPAD*G3];
__device__ float d_h0b   [2*Bc*Hc];
__device__ float d_h1b   [2*Bc*Hc];
__device__ float d_ctxb  [2*Bc*Hc];
__device__ float d_qb    [Bc*Ac];
__device__ float d_feat  [MBc*2*Hc];
__device__ unsigned d_bars[4];
// bf16 split operand buffers
__device__ __nv_bfloat16 d_Ah[4096*1024];
__device__ __nv_bfloat16 d_Al[4096*1024];
__device__ __nv_bfloat16 d_Wh[3072*1024];
__device__ __nv_bfloat16 d_Wl[3072*1024];
__device__ __nv_bfloat16 d_Bh[(size_t)Vc*1024];
__device__ __nv_bfloat16 d_Bl[(size_t)Vc*1024];

// ---------------- grid barrier (all blocks must be co-resident: grid <= 148) ---------------
__device__ __forceinline__ void gbar(unsigned* cnt, unsigned target) {
    __threadfence();
    __syncthreads();
    if (threadIdx.x == 0) {
        unsigned v;
        asm volatile("red.release.gpu.global.add.u32 [%0], 1;" :: "l"(cnt) : "memory");
        do {
            asm volatile("ld.acquire.gpu.global.u32 %0, [%1];" : "=r"(v) : "l"(cnt) : "memory");
        } while (v < target);
    }
    __syncthreads();
}

// ---------------- embedding gathers ----------------
__global__ void gather_rows(const int* __restrict__ tok, const float* __restrict__ tab,
                            float* __restrict__ out, int mode)
{
    int row = blockIdx.x;
    int idx;
    if (mode == 0) idx = tok[row];
    else { int t = row >> 5, b = row & 31; idx = tok[b*Tc + t]; }
    const float4* src = (const float4*)(tab + (size_t)idx * Ec);
    float4* dst = (float4*)(out + (size_t)row * Ec);
    dst[threadIdx.x] = src[threadIdx.x];
}

// ---------------- fp32 -> split bf16 ----------------
__global__ void conv_split(const float* __restrict__ in, __nv_bfloat16* __restrict__ hi,
                           __nv_bfloat16* __restrict__ lo, long n_valid, long n_total)
{
    long i = (long)blockIdx.x * blockDim.x + threadIdx.x;
    if (i >= n_total) return;
    float v = (i < n_valid) ? in[i] : 0.f;
    __nv_bfloat16 h = __float2bfloat16(v);
    hi[i] = h;
    lo[i] = __float2bfloat16(v - __bfloat162float(h));
}
__global__ void conv_split2d(const float* __restrict__ in, int ld, int rows, int cols,
                             __nv_bfloat16* __restrict__ hi, __nv_bfloat16* __restrict__ lo)
{
    long i = (long)blockIdx.x * blockDim.x + threadIdx.x;
    if (i >= (long)rows * cols) return;
    int r = (int)(i / cols), c = (int)(i % cols);
    float v = in[(size_t)r * ld + c];
    __nv_bfloat16 h = __float2bfloat16(v);
    hi[i] = h;
    lo[i] = __float2bfloat16(v - __bfloat162float(h));
}

// =============== generic split-bf16 tensor GEMM (unchanged from R7) ===============
#define F_RELU  1
#define F_REMAP 2
#define F_SPLIT 4
#define SLDA 40
#define TILEB (128*SLDA*2)
#define STAGEB (4*TILEB)
#define GEMM_SMEM (2*STAGEB)

__device__ __forceinline__ uint32_t smem_u32(const void* p) {
    uint32_t a;
    asm("{ .reg .u64 t; cvta.to.shared.u64 t, %1; cvt.u32.u64 %0, t; }" : "=r"(a) : "l"(p));
    return a;
}
__device__ __forceinline__ void ldm4(uint32_t& r0, uint32_t& r1, uint32_t& r2, uint32_t& r3, uint32_t a) {
    asm volatile("ldmatrix.sync.aligned.m8n8.x4.shared.b16 {%0,%1,%2,%3}, [%4];"
                 : "=r"(r0), "=r"(r1), "=r"(r2), "=r"(r3) : "r"(a));
}
__device__ __forceinline__ void mma16816(float* c, const uint32_t* a, const uint32_t* b) {
    asm volatile("mma.sync.aligned.m16n8k16.row.col.f32.bf16.bf16.f32 "
                 "{%0,%1,%2,%3},{%4,%5,%6,%7},{%8,%9},{%0,%1,%2,%3};"
                 : "+f"(c[0]), "+f"(c[1]), "+f"(c[2]), "+f"(c[3])
                 : "r"(a[0]), "r"(a[1]), "r"(a[2]), "r"(a[3]), "r"(b[0]), "r"(b[1]));
}
#define CP16(dst, src) asm volatile("cp.async.cg.shared.global [%0], [%1], 16;" :: "r"(dst), "l"(src))
#define CP_COMMIT()    asm volatile("cp.async.commit_group;" ::: "memory")
#define CP_WAIT1()     asm volatile("cp.async.wait_group 1;" ::: "memory")

__global__ __launch_bounds__(256) void gemm_bf16(
    int K,
    const __nv_bfloat16* __restrict__ Ah, const __nv_bfloat16* __restrict__ Al,
    const __nv_bfloat16* __restrict__ Bh, const __nv_bfloat16* __restrict__ Bl,
    const float* __restrict__ bias,
    float* __restrict__ Cf, __nv_bfloat16* __restrict__ Chi, __nv_bfloat16* __restrict__ Clo,
    int ldc, int flags)
{
    extern __shared__ char smem[];
    const uint32_t smem_base = smem_u32(smem);
    const int tid = threadIdx.x, wid = tid >> 5, lane = tid & 31;
    const int nBase = blockIdx.x * 128;
    const int mBase = blockIdx.y * 128;
    const int warpM = (wid & 1) * 64;
    const int warpN = (wid >> 1) * 32;

    const __nv_bfloat16* g[4] = {
        Ah + (size_t)mBase * K, Al + (size_t)mBase * K,
        Bh + (size_t)nBase * K, Bl + (size_t)nBase * K };

    const int lRow0 = tid >> 2, lSc0 = (tid & 3);
    const int lRow1 = (tid + 256) >> 2, lSc1 = ((tid + 256) & 3);

    auto prefetch = [&](int st, int kc) {
        #pragma unroll
        for (int op = 0; op < 4; op++) {
            uint32_t sb = smem_base + st * STAGEB + op * TILEB;
            CP16(sb + (uint32_t)(lRow0 * SLDA + lSc0 * 8) * 2, g[op] + (size_t)lRow0 * K + kc + lSc0 * 8);
            CP16(sb + (uint32_t)(lRow1 * SLDA + lSc1 * 8) * 2, g[op] + (size_t)lRow1 * K + kc + lSc1 * 8);
        }
    };

    float acc[4][4][4];
    #pragma unroll
    for (int i = 0; i < 4; i++)
        #pragma unroll
        for (int j = 0; j < 4; j++)
            #pragma unroll
            for (int e = 0; e < 4; e++) acc[i][j][e] = 0.f;

    const int aRow = (lane & 15), aK = (lane >> 4) * 8;
    const int bRow = ((lane >> 4) << 3) + (lane & 7), bK = ((lane >> 3) & 1) * 8;

    const int nch = K >> 5;
    prefetch(0, 0);
    CP_COMMIT();

    for (int c = 0; c < nch; c++) {
        if (c + 1 < nch) prefetch((c + 1) & 1, (c + 1) << 5);
        CP_COMMIT();
        CP_WAIT1();
        __syncthreads();

        const uint32_t stb = smem_base + (c & 1) * STAGEB;
        const uint32_t bAh = stb, bAl = stb + TILEB, bBh = stb + 2*TILEB, bBl = stb + 3*TILEB;

        #pragma unroll
        for (int ks = 0; ks < 2; ks++) {
            const int kb = ks * 16;
            uint32_t fbh[4][2], fbl[4][2];
            #pragma unroll
            for (int nt = 0; nt < 2; nt++) {
                uint32_t off = ((uint32_t)(warpN + nt * 16 + bRow) * SLDA + kb + bK) * 2;
                ldm4(fbh[nt*2][0], fbh[nt*2][1], fbh[nt*2+1][0], fbh[nt*2+1][1], bBh + off);
                ldm4(fbl[nt*2][0], fbl[nt*2][1], fbl[nt*2+1][0], fbl[nt*2+1][1], bBl + off);
            }
            #pragma unroll
            for (int mi = 0; mi < 4; mi++) {
                uint32_t fah[4], fal[4];
                uint32_t off = ((uint32_t)(warpM + mi * 16 + aRow) * SLDA + kb + aK) * 2;
                ldm4(fah[0], fah[1], fah[2], fah[3], bAh + off);
                ldm4(fal[0], fal[1], fal[2], fal[3], bAl + off);
                #pragma unroll
                for (int ni = 0; ni < 4; ni++) {
                    mma16816(acc[mi][ni], fah, fbh[ni]);
                    mma16816(acc[mi][ni], fah, fbl[ni]);
                    mma16816(acc[mi][ni], fal, fbh[ni]);
                }
            }
        }
        __syncthreads();
    }

    const int mLane = lane >> 2;
    const int nLane = (lane & 3) * 2;
    #pragma unroll
    for (int mi = 0; mi < 4; mi++) {
        #pragma unroll
        for (int half = 0; half < 2; half++) {
            int m = mBase + warpM + mi * 16 + mLane + half * 8;
            int orow = m;
            if (flags & F_REMAP) {
                if (m >= MBc) continue;
                orow = (m & 31) * TDc + (m >> 5);
            }
            #pragma unroll
            for (int ni = 0; ni < 4; ni++) {
                int n = nBase + warpN + ni * 8 + nLane;
                float vx = acc[mi][ni][half * 2 + 0] + bias[n];
                float vy = acc[mi][ni][half * 2 + 1] + bias[n + 1];
                if (flags & F_RELU) { vx = fmaxf(vx, 0.f); vy = fmaxf(vy, 0.f); }
                if (flags & F_SPLIT) {
                    size_t o = (size_t)orow * ldc + n;
                    __nv_bfloat16 hx = __float2bfloat16(vx), hy = __float2bfloat16(vy);
                    Chi[o] = hx; Chi[o+1] = hy;
                    Clo[o]   = __float2bfloat16(vx - __bfloat162float(hx));
                    Clo[o+1] = __float2bfloat16(vy - __bfloat162float(hy));
                } else {
                    *(float2*)(Cf + (size_t)orow * ldc + n) = make_float2(vx, vy);
                }
            }
        }
    }
}

// ---------------- shared helpers for recurrent kernels ----------------
__device__ __forceinline__ void gate3_chunk(
    const float (*hs)[132], int row, const float* pr, const float* pz, const float* pn,
    float& a0, float& a1, float& a2)
{
    #pragma unroll 8
    for (int k = 0; k < 128; k += 4) {
        float4 hv = *(const float4*)&hs[row][k];
        float4 w4;
        w4 = *(const float4*)&pr[k]; a0 += hv.x*w4.x + hv.y*w4.y + hv.z*w4.z + hv.w*w4.w;
        w4 = *(const float4*)&pz[k]; a1 += hv.x*w4.x + hv.y*w4.y + hv.z*w4.z + hv.w*w4.w;
        w4 = *(const float4*)&pn[k]; a2 += hv.x*w4.x + hv.y*w4.y + hv.z*w4.z + hv.w*w4.w;
    }
}
__device__ __forceinline__ void stage_tile(float (*hs)[132], const float* src, int kc, int nthr, int tid) {
    for (int i = tid; i < 1024; i += nthr) {
        int r = i >> 5, kk = (i & 31) << 2;
        *(float4*)&hs[r][kk] = *(const float4*)&src[(size_t)r*Hc + kc + kk];
    }
}

// =============== persistent encoder GRU layer: 128 blocks, 128 steps internal ===============
#define ENC_SMEM (49152 + 32*132*4)
__global__ __launch_bounds__(256) void enc_gru_persist(
    const float* __restrict__ gi, const float* __restrict__ WhhBase,
    const float* __restrict__ bhhBase, float* __restrict__ y, unsigned* bar)
{
    extern __shared__ char sm[];
    float* wsm = (float*)sm;                            // [3][8][512]
    float (*hs)[132] = (float(*)[132])(sm + 49152);
    const int tid = threadIdx.x, wid = tid >> 5, row = tid & 31;
    const int dir = blockIdx.x >> 6;
    const int jb  = blockIdx.x & 63;
    const int j   = jb * 8 + wid;
    const int dcol = dir * Hc;
    const float* Whh = WhhBase + (size_t)dir * G3 * Hc;
    const float* bhh = bhhBase + dir * G3;

    for (int i = tid; i < 3*8*512; i += 256) {
        int g = i >> 12, rem = i & 4095, w = rem >> 9, k = rem & 511;
        wsm[i] = Whh[(size_t)(g*Hc + jb*8 + w)*Hc + k];
    }
    const float b0 = bhh[j], b1 = bhh[Hc + j], b2 = bhh[2*Hc + j];
    __syncthreads();

    for (int s = 0; s < Lc; s++) {
        const int te = dir ? (Lc - 1 - s) : s;
        const int tprev = dir ? (te + 1) : (te - 1);
        const bool first = (s == 0);
        float ar = 0.f, az = 0.f, an = 0.f;
        for (int kc = 0; kc < Hc; kc += 128) {
            for (int i = tid; i < 1024; i += 256) {
                int r = i >> 5, kk = (i & 31) << 2;
                float4 v = make_float4(0,0,0,0);
                if (!first) v = *(const float4*)&y[((size_t)tprev*Bc + r)*(2*Hc) + dcol + kc + kk];
                *(float4*)&hs[r][kk] = v;
            }
            __syncthreads();
            gate3_chunk(hs, row, wsm + wid*512 + kc, wsm + 4096 + wid*512 + kc,
                        wsm + 8192 + wid*512 + kc, ar, az, an);
            __syncthreads();
        }
        const float* gp = gi + ((size_t)te*Bc + row) * (2*G3) + dir * G3;
        float rg = 1.f / (1.f + __expf(-(gp[j]      + ar + b0)));
        float zg = 1.f / (1.f + __expf(-(gp[Hc + j] + az + b1)));
        float ng = tanhf(gp[2*Hc + j] + rg * (an + b2));
        float hp = first ? 0.f : y[((size_t)tprev*Bc + row)*(2*Hc) + dcol + j];
        y[((size_t)te*Bc + row)*(2*Hc) + dcol + j] = (1.f - zg)*ng + zg*hp;
        if (s < Lc - 1) gbar(bar, 128u * (unsigned)(s + 1));
    }
}

// ---------------- enc_out = y1[:, :H] + y1[:, H:] ----------------
__global__ void combine_enc(const float* __restrict__ y1, float* __restrict__ eo)
{
    int i = blockIdx.x;
    int h = threadIdx.x * 4;
    float4 a = *(const float4*)&y1[(size_t)i*2*Hc + h];
    float4 b = *(const float4*)&y1[(size_t)i*2*Hc + Hc + h];
    *(float4*)&eo[(size_t)i*Hc + h] = make_float4(a.x+b.x, a.y+b.y, a.z+b.z, a.w+b.w);
}

// =============== persistent decoder: 128 blocks x 128 thr, 63 steps x 4 phases ===============
#define DEC_SMEM (4*24576 + 8192 + 32*132*4 + (512+128+4)*4)
__global__ __launch_bounds__(128) void dec_persist(
    const float* __restrict__ dWih0, const float* __restrict__ dWhh0,
    const float* __restrict__ bhh0,
    const float* __restrict__ dWih1, const float* __restrict__ dWhh1,
    const float* __restrict__ bih1, const float* __restrict__ bhh1,
    const float* __restrict__ Wd, const float* __restrict__ bd,
    const float* __restrict__ dpre,
    const float* __restrict__ encq, const float* __restrict__ encout,
    float* __restrict__ h0b, float* __restrict__ h1b, float* __restrict__ ctxb,
    float* __restrict__ qb, float* __restrict__ feat, unsigned* bar)
{
    extern __shared__ char sm[];
    float* wx0 = (float*)sm;                 // each [3][4][512] = 6144 floats
    float* wh0 = wx0 + 6144;
    float* wx1 = wh0 + 6144;
    float* wh1 = wx1 + 6144;
    float* wd  = wh1 + 6144;                 // [4][512]
    float (*hs)[132] = (float(*)[132])(wd + 2048);
    float* qs   = (float*)hs + 32*132;       // 512
    float* es   = qs + 512;                  // 128
    float* ssum = es + 128;                  // 4

    const int tid = threadIdx.x, w = tid >> 5, lane = tid & 31, row = lane;
    const int blk = blockIdx.x;
    const int j = blk * 4 + w;

    // cache weights (once)
    for (int i = tid; i < 6144; i += 128) {
        int g = i / 2048, rem = i - g*2048, ww = rem >> 9, k = rem & 511;
        int r0 = g*Hc + blk*4 + ww;
        wx0[i] = dWih0[(size_t)r0*(Ec + Hc) + Ec + k];
        wh0[i] = dWhh0[(size_t)r0*Hc + k];
        wx1[i] = dWih1[(size_t)r0*Hc + k];
        wh1[i] = dWhh1[(size_t)r0*Hc + k];
    }
    for (int i = tid; i < 2048; i += 128)
        wd[i] = Wd[(size_t)(blk*4 + (i >> 9))*Hc + (i & 511)];
    const float bh0r = bhh0[j], bh0z = bhh0[Hc+j], bh0n = bhh0[2*Hc+j];
    const float bi1r = bih1[j], bi1z = bih1[Hc+j], bi1n = bih1[2*Hc+j];
    const float bh1r = bhh1[j], bh1z = bhh1[Hc+j], bh1n = bhh1[2*Hc+j];
    const float bdj = bd[j];
    __syncthreads();

    unsigned bi = 0;
    for (int t = 0; t < TDc; t++) {
        const int r = t & 1, wix = 1 - r;
        const float* ctxp = ctxb + (size_t)r*Bc*Hc;
        const float* h0p  = h0b  + (size_t)r*Bc*Hc;
        float*       h0n  = h0b  + (size_t)wix*Bc*Hc;
        const float* h1p  = h1b  + (size_t)r*Bc*Hc;
        float*       h1n  = h1b  + (size_t)wix*Bc*Hc;

        // ---- phase 1: cell0 (x=ctx, h=h0) ----
        {
            float air=0.f, aiz=0.f, ain=0.f, ahr=0.f, ahz=0.f, ahn=0.f;
            for (int kc = 0; kc < Hc; kc += 128) {
                stage_tile(hs, ctxp, kc, 128, tid);
                __syncthreads();
                gate3_chunk(hs, row, wx0 + w*512 + kc, wx0 + 2048 + w*512 + kc,
                            wx0 + 4096 + w*512 + kc, air, aiz, ain);
                __syncthreads();
            }
            for (int kc = 0; kc < Hc; kc += 128) {
                stage_tile(hs, h0p, kc, 128, tid);
                __syncthreads();
                gate3_chunk(hs, row, wh0 + w*512 + kc, wh0 + 2048 + w*512 + kc,
                            wh0 + 4096 + w*512 + kc, ahr, ahz, ahn);
                __syncthreads();
            }
            const float* pre = dpre + ((size_t)t*Bc + row)*G3;
            float rg = 1.f / (1.f + __expf(-(air + pre[j]      + ahr + bh0r)));
            float zg = 1.f / (1.f + __expf(-(aiz + pre[Hc+j]   + ahz + bh0z)));
            float ng = tanhf(ain + pre[2*Hc+j] + rg * (ahn + bh0n));
            h0n[(size_t)row*Hc + j] = (1.f - zg)*ng + zg*h0p[(size_t)row*Hc + j];
        }
        gbar(bar, 128u * (++bi));

        // ---- phase 2: cell1 (x=h0n, h=h1) ----
        {
            float air=0.f, aiz=0.f, ain=0.f, ahr=0.f, ahz=0.f, ahn=0.f;
            for (int kc = 0; kc < Hc; kc += 128) {
                stage_tile(hs, h0n, kc, 128, tid);
                __syncthreads();
                gate3_chunk(hs, row, wx1 + w*512 + kc, wx1 + 2048 + w*512 + kc,
                            wx1 + 4096 + w*512 + kc, air, aiz, ain);
                __syncthreads();
            }
            for (int kc = 0; kc < Hc; kc += 128) {
                stage_tile(hs, h1p, kc, 128, tid);
                __syncthreads();
                gate3_chunk(hs, row, wh1 + w*512 + kc, wh1 + 2048 + w*512 + kc,
                            wh1 + 4096 + w*512 + kc, ahr, ahz, ahn);
                __syncthreads();
            }
            float rg = 1.f / (1.f + __expf(-(air + bi1r + ahr + bh1r)));
            float zg = 1.f / (1.f + __expf(-(aiz + bi1z + ahz + bh1z)));
            float ng = tanhf(ain + bi1n + rg * (ahn + bh1n));
            h1n[(size_t)row*Hc + j] = (1.f - zg)*ng + zg*h1p[(size_t)row*Hc + j];
        }
        gbar(bar, 128u * (++bi));

        // ---- phase 3: q = h1n @ Wd^T + bd ----
        {
            float acc = 0.f;
            for (int kc = 0; kc < Hc; kc += 128) {
                stage_tile(hs, h1n, kc, 128, tid);
                __syncthreads();
                const float* wj = wd + w*512 + kc;
                #pragma unroll 8
                for (int k = 0; k < 128; k += 4) {
                    float4 hv = *(const float4*)&hs[row][k];
                    float4 w4 = *(const float4*)&wj[k];
                    acc += hv.x*w4.x + hv.y*w4.y + hv.z*w4.z + hv.w*w4.w;
                }
                __syncthreads();
            }
            qb[(size_t)row*Hc + j] = acc + bdj;
        }
        gbar(bar, 128u * (++bi));

        // ---- phase 4: attention + feat (blocks 0..31, b = blk) ----
        if (blk < 32) {
            const int b = blk;
            qs[tid]       = qb[(size_t)b*Hc + tid];
            qs[tid + 128] = qb[(size_t)b*Hc + tid + 128];
            qs[tid + 256] = qb[(size_t)b*Hc + tid + 256];
            qs[tid + 384] = qb[(size_t)b*Hc + tid + 384];
            __syncthreads();
            for (int l = w; l < Lc; l += 4) {
                const float* eqr = encq + ((size_t)l*Bc + b) * Ac;
                float s = 0.f;
                #pragma unroll
                for (int qk = 0; qk < 4; qk++) {
                    int k = qk*128 + lane*4;
                    float4 a = *(const float4*)&eqr[k];
                    float4 c = *(const float4*)&qs[k];
                    s += a.x*c.x + a.y*c.y + a.z*c.z + a.w*c.w;
                }
                #pragma unroll
                for (int off = 16; off; off >>= 1) s += __shfl_xor_sync(0xffffffffu, s, off);
                if (lane == 0) es[l] = __expf(tanhf(s));
            }
            __syncthreads();
            {
                float v = es[tid];
                #pragma unroll
                for (int off = 16; off; off >>= 1) v += __shfl_xor_sync(0xffffffffu, v, off);
                if (lane == 0) ssum[w] = v;
            }
            __syncthreads();
            float inv = 1.f / (ssum[0] + ssum[1] + ssum[2] + ssum[3]);
            float a0=0.f, a1=0.f, a2=0.f, a3=0.f;
            for (int l = 0; l < Lc; l++) {
                float wl = es[l];
                const float* eor = encout + ((size_t)l*Bc + b) * Hc;
                a0 += wl*eor[tid]; a1 += wl*eor[tid+128]; a2 += wl*eor[tid+256]; a3 += wl*eor[tid+384];
            }
            a0 *= inv; a1 *= inv; a2 *= inv; a3 *= inv;
            float* cx = ctxb + (size_t)wix*Bc*Hc + (size_t)b*Hc;
            cx[tid]=a0; cx[tid+128]=a1; cx[tid+256]=a2; cx[tid+384]=a3;
            float* fp = feat + ((size_t)t*Bc + b) * 2*Hc;
            const float* h1r = h1n + (size_t)b*Hc;
            fp[tid]=h1r[tid]; fp[tid+128]=h1r[tid+128]; fp[tid+256]=h1r[tid+256]; fp[tid+384]=h1r[tid+384];
            fp[Hc+tid]=a0; fp[Hc+tid+128]=a1; fp[Hc+tid+256]=a2; fp[Hc+tid+384]=a3;
            __syncthreads();
        }
        ++bi;
        if (t < TDc - 1) gbar(bar, 128u * bi);
    }
}

// ================================================================================
extern "C" void kernel_launch(void* const* d_in, const int* in_sizes, int n_in,
                              void* d_out, int out_size)
{
    const int*   src_tokens = (const int*)  d_in[0];
    const int*   trgt_seq   = (const int*)  d_in[1];
    const float* enc_embed  = (const float*)d_in[3];
    const float* enc_Wih0   = (const float*)d_in[4];
    const float* enc_Whh0   = (const float*)d_in[5];
    const float* enc_bih0   = (const float*)d_in[6];
    const float* enc_bhh0   = (const float*)d_in[7];
    const float* enc_Wih1   = (const float*)d_in[8];
    const float* enc_Whh1   = (const float*)d_in[9];
    const float* enc_bih1   = (const float*)d_in[10];
    const float* enc_bhh1   = (const float*)d_in[11];
    const float* dec_embed  = (const float*)d_in[12];
    const float* dec_Wih0   = (const float*)d_in[13];
    const float* dec_Whh0   = (const float*)d_in[14];
    const float* dec_bih0   = (const float*)d_in[15];
    const float* dec_bhh0   = (const float*)d_in[16];
    const float* dec_Wih1   = (const float*)d_in[17];
    const float* dec_Whh1   = (const float*)d_in[18];
    const float* dec_bih1   = (const float*)d_in[19];
    const float* dec_bhh1   = (const float*)d_in[20];
    const float* attn_We    = (const float*)d_in[21];
    const float* attn_be    = (const float*)d_in[22];
    const float* attn_Wd    = (const float*)d_in[23];
    const float* attn_bd    = (const float*)d_in[24];
    const float* mlp_W1     = (const float*)d_in[25];
    const float* mlp_b1     = (const float*)d_in[26];
    const float* mlp_W2     = (const float*)d_in[27];
    const float* mlp_b2     = (const float*)d_in[28];

    float *emb, *decemb, *gi, *y0, *y1, *eo, *eq, *dpre, *h0b, *h1b, *ctxb, *qb, *feat;
    unsigned* bars;
    __nv_bfloat16 *Ah, *Al, *Wh, *Wl, *Bh, *Bl;
    cudaGetSymbolAddress((void**)&emb,    d_emb);
    cudaGetSymbolAddress((void**)&decemb, d_decemb);
    cudaGetSymbolAddress((void**)&gi,     d_gi);
    cudaGetSymbolAddress((void**)&y0,     d_y0);
    cudaGetSymbolAddress((void**)&y1,     d_y1);
    cudaGetSymbolAddress((void**)&eo,     d_eo);
    cudaGetSymbolAddress((void**)&eq,     d_eq);
    cudaGetSymbolAddress((void**)&dpre,   d_dpre);
    cudaGetSymbolAddress((void**)&h0b,    d_h0b);
    cudaGetSymbolAddress((void**)&h1b,    d_h1b);
    cudaGetSymbolAddress((void**)&ctxb,   d_ctxb);
    cudaGetSymbolAddress((void**)&qb,     d_qb);
    cudaGetSymbolAddress((void**)&feat,   d_feat);
    cudaGetSymbolAddress((void**)&bars,   d_bars);
    cudaGetSymbolAddress((void**)&Ah,     d_Ah);
    cudaGetSymbolAddress((void**)&Al,     d_Al);
    cudaGetSymbolAddress((void**)&Wh,     d_Wh);
    cudaGetSymbolAddress((void**)&Wl,     d_Wl);
    cudaGetSymbolAddress((void**)&Bh,     d_Bh);
    cudaGetSymbolAddress((void**)&Bl,     d_Bl);

    cudaFuncSetAttribute(gemm_bf16,       cudaFuncAttributeMaxDynamicSharedMemorySize, GEMM_SMEM);
    cudaFuncSetAttribute(enc_gru_persist, cudaFuncAttributeMaxDynamicSharedMemorySize, ENC_SMEM);
    cudaFuncSetAttribute(dec_persist,     cudaFuncAttributeMaxDynamicSharedMemorySize, DEC_SMEM);

    cudaMemsetAsync(bars, 0, 4*sizeof(unsigned));
    cudaMemsetAsync(h0b,  0, Bc*Hc*sizeof(float));
    cudaMemsetAsync(h1b,  0, Bc*Hc*sizeof(float));
    cudaMemsetAsync(ctxb, 0, Bc*Hc*sizeof(float));

    // embeddings
    gather_rows<<<Lc*Bc, 128>>>(src_tokens, enc_embed, emb, 0);
    gather_rows<<<MBc,   128>>>(trgt_seq,   dec_embed, decemb, 1);

    // mlp_W2 conversion
    { long n = (long)Vc * 1024; conv_split<<<(unsigned)(n/256), 256>>>(mlp_W2, Bh, Bl, n, n); }

    // ===== encoder layer0 pre + persistent recurrence =====
    { long n = (long)Lc*Bc*Ec;  conv_split<<<(unsigned)(n/256), 256>>>(emb, Ah, Al, n, n); }
    { long n = (long)2*G3*Ec;   conv_split<<<(unsigned)(n/256), 256>>>(enc_Wih0, Wh, Wl, n, n); }
    gemm_bf16<<<dim3(2*G3/128, Lc*Bc/128), 256, GEMM_SMEM>>>(
        Ec, Ah, Al, Wh, Wl, enc_bih0, gi, nullptr, nullptr, 2*G3, 0);
    enc_gru_persist<<<128, 256, ENC_SMEM>>>(gi, enc_Whh0, enc_bhh0, y0, bars + 0);

    // ===== encoder layer1 =====
    { long n = (long)Lc*Bc*2*Hc; conv_split<<<(unsigned)(n/256), 256>>>(y0, Ah, Al, n, n); }
    { long n = (long)2*G3*2*Hc;  conv_split<<<(unsigned)(n/256), 256>>>(enc_Wih1, Wh, Wl, n, n); }
    gemm_bf16<<<dim3(2*G3/128, Lc*Bc/128), 256, GEMM_SMEM>>>(
        2*Hc, Ah, Al, Wh, Wl, enc_bih1, gi, nullptr, nullptr, 2*G3, 0);
    enc_gru_persist<<<128, 256, ENC_SMEM>>>(gi, enc_Whh1, enc_bhh1, y1, bars + 1);

    combine_enc<<<Lc*Bc, 128>>>(y1, eo);

    // ===== enc_q =====
    { long n = (long)Lc*Bc*Hc; conv_split<<<(unsigned)(n/256), 256>>>(eo, Ah, Al, n, n); }
    { long n = (long)Ac*Hc;    conv_split<<<(unsigned)(n/256), 256>>>(attn_We, Wh, Wl, n, n); }
    gemm_bf16<<<dim3(Ac/128, Lc*Bc/128), 256, GEMM_SMEM>>>(
        Hc, Ah, Al, Wh, Wl, attn_be, eq, nullptr, nullptr, Ac, 0);

    // ===== decoder pre =====
    { long nv = (long)MBc*Ec, nt = (long)MPAD*Ec;
      conv_split<<<(unsigned)(nt/256), 256>>>(decemb, Ah, Al, nv, nt); }
    { long n = (long)G3*Ec;
      conv_split2d<<<(unsigned)(n/256), 256>>>(dec_Wih0, Ec + Hc, G3, Ec, Wh, Wl); }
    gemm_bf16<<<dim3(G3/128, MPAD/128), 256, GEMM_SMEM>>>(
        Ec, Ah, Al, Wh, Wl, dec_bih0, dpre, nullptr, nullptr, G3, 0);

    // ===== persistent decoder (63 steps, 4 phases each) =====
    dec_persist<<<128, 128, DEC_SMEM>>>(
        dec_Wih0, dec_Whh0, dec_bhh0,
        dec_Wih1, dec_Whh1, dec_bih1, dec_bhh1,
        attn_Wd, attn_bd, dpre, eq, eo,
        h0b, h1b, ctxb, qb, feat, bars + 2);

    // ===== MLP1 (split-bf16 out) =====
    { long nv = (long)MBc*2*Hc, nt = (long)MPAD*2*Hc;
      conv_split<<<(unsigned)(nt/256), 256>>>(feat, Ah, Al, nv, nt); }
    { long n = (long)2*Hc*2*Hc; conv_split<<<(unsigned)(n/256), 256>>>(mlp_W1, Wh, Wl, n, n); }
    __nv_bfloat16* Ah2 = Ah + (size_t)MPAD * 1024;
    __nv_bfloat16* Al2 = Al + (size_t)MPAD * 1024;
    gemm_bf16<<<dim3(2*Hc/128, MPAD/128), 256, GEMM_SMEM>>>(
        2*Hc, Ah, Al, Wh, Wl, mlp_b1, nullptr, Ah2, Al2, 2*Hc, F_RELU | F_SPLIT);

    // ===== MLP2 logits =====
    gemm_bf16<<<dim3(Vc/128, MPAD/128), 256, GEMM_SMEM>>>(
        2*Hc, Ah2, Al2, Bh, Bl, mlp_b2, (float*)d_out, nullptr, nullptr, Vc, F_REMAP);
}